// round 3
// baseline (speedup 1.0000x reference)
#include <cuda_runtime.h>
#include <cuda_bf16.h>
#include <math.h>

// Problem dims (fixed by dataset)
#define BB 2
#define SS 2048
#define DD 768
#define HH 12
#define HD 64
#define DFF 3072
#define MM (BB * SS)   // 4096 tokens

// ---------------- scratch (no allocations allowed) ----------------
__device__ __align__(16) float g_q[MM * DD];
__device__ __align__(16) float g_k[MM * DD];
__device__ __align__(16) float g_v[MM * DD];
__device__ __align__(16) float g_attn[MM * DD];
__device__ __align__(16) float g_proj[MM * DD];
__device__ __align__(16) float g_x1[MM * DD];
__device__ __align__(16) float g_ff[MM * DFF];
__device__ __align__(16) float g_ff2[MM * DD];

// ---------------- SGEMM: C[M,N] = A[M,K] @ B[N,K]^T + bias (+gelu) ----------
// A row-major [M,K], B row-major [N,K] (torch Linear weight layout).
// BM=BN=128, BK=8, TM=TN=8, 256 threads. All shapes divide evenly here.
template<int GELU>
__global__ __launch_bounds__(256, 2)
void sgemm_nt(int M, int N, int K,
              const float* __restrict__ A,
              const float* __restrict__ B,
              const float* __restrict__ bias,
              float* __restrict__ C)
{
    constexpr int BM = 128, BN = 128, BK = 8, TM = 8, TN = 8;
    __shared__ float As[BK][BM];
    __shared__ float Bs[BK][BN];

    const int tid  = threadIdx.x;
    const int crow = blockIdx.y;   // M tile
    const int ccol = blockIdx.x;   // N tile
    const int trow = (tid / 16) * TM;
    const int tcol = (tid % 16) * TN;

    const float* Ag = A + (size_t)crow * BM * K;
    const float* Bg = B + (size_t)ccol * BN * K;

    const int lrow = tid >> 1;          // 0..127
    const int lcol = (tid & 1) << 2;    // 0 or 4

    float acc[TM][TN];
    #pragma unroll
    for (int i = 0; i < TM; ++i)
        #pragma unroll
        for (int j = 0; j < TN; ++j) acc[i][j] = 0.f;

    for (int k0 = 0; k0 < K; k0 += BK) {
        float4 a4 = *reinterpret_cast<const float4*>(Ag + (size_t)lrow * K + k0 + lcol);
        float4 b4 = *reinterpret_cast<const float4*>(Bg + (size_t)lrow * K + k0 + lcol);
        As[lcol + 0][lrow] = a4.x; As[lcol + 1][lrow] = a4.y;
        As[lcol + 2][lrow] = a4.z; As[lcol + 3][lrow] = a4.w;
        Bs[lcol + 0][lrow] = b4.x; Bs[lcol + 1][lrow] = b4.y;
        Bs[lcol + 2][lrow] = b4.z; Bs[lcol + 3][lrow] = b4.w;
        __syncthreads();

        #pragma unroll
        for (int k = 0; k < BK; ++k) {
            float rm[TM], rn[TN];
            #pragma unroll
            for (int i = 0; i < TM; ++i) rm[i] = As[k][trow + i];
            #pragma unroll
            for (int j = 0; j < TN; ++j) rn[j] = Bs[k][tcol + j];
            #pragma unroll
            for (int i = 0; i < TM; ++i)
                #pragma unroll
                for (int j = 0; j < TN; ++j)
                    acc[i][j] = fmaf(rm[i], rn[j], acc[i][j]);
        }
        __syncthreads();
    }

    #pragma unroll
    for (int i = 0; i < TM; ++i) {
        const int row = crow * BM + trow + i;
        #pragma unroll
        for (int j4 = 0; j4 < TN; j4 += 4) {
            const int col = ccol * BN + tcol + j4;
            float4 o;
            float* ov = &o.x;
            #pragma unroll
            for (int j = 0; j < 4; ++j) {
                float v = acc[i][j4 + j] + bias[col + j];
                if (GELU) v = 0.5f * v * (1.f + erff(v * 0.70710678118654752f));
                ov[j] = v;
            }
            *reinterpret_cast<float4*>(C + (size_t)row * N + col) = o;
        }
    }
}

// ---------------- Attention: flash-style, one thread per query row ----------
// q,k,v are [B,S,D] with head slice at h*HD. Output h[b,s,h*HD+d] (= bqhd).
__global__ __launch_bounds__(128)
void attn_kernel(const float* __restrict__ q,
                 const float* __restrict__ k,
                 const float* __restrict__ v,
                 const float* __restrict__ mask,
                 float* __restrict__ out)
{
    constexpr int KT = 32;
    const int b   = blockIdx.z;
    const int h   = blockIdx.y;
    const int tid = threadIdx.x;
    const int row = blockIdx.x * 128 + tid;   // query index in [0,S)

    __shared__ float Ks[KT][HD];
    __shared__ float Vs[KT][HD];
    __shared__ float msk[KT];

    float qr[HD];
    const float* qp = q + ((size_t)b * SS + row) * DD + h * HD;
    #pragma unroll
    for (int d = 0; d < HD; ++d) qr[d] = qp[d] * 0.125f;   // 1/sqrt(64)

    float acc[HD];
    #pragma unroll
    for (int d = 0; d < HD; ++d) acc[d] = 0.f;
    float mx = -1e30f, l = 0.f;

    for (int kt = 0; kt < SS; kt += KT) {
        __syncthreads();
        // load K,V tile: KT*HD floats = 512 float4s, 4 per thread, coalesced
        #pragma unroll
        for (int i = 0; i < 4; ++i) {
            const int f4 = i * 128 + tid;
            const int r  = f4 >> 4;          // /16 float4 per row
            const int c  = (f4 & 15) << 2;   // *4
            const size_t gofs = ((size_t)b * SS + kt + r) * DD + h * HD + c;
            *reinterpret_cast<float4*>(&Ks[r][c]) =
                *reinterpret_cast<const float4*>(k + gofs);
            *reinterpret_cast<float4*>(&Vs[r][c]) =
                *reinterpret_cast<const float4*>(v + gofs);
        }
        if (tid < KT) msk[tid] = -10000.f * (1.f - mask[(size_t)b * SS + kt + tid]);
        __syncthreads();

        float s[KT];
        float tmax = mx;
        #pragma unroll
        for (int kk = 0; kk < KT; ++kk) {
            float sum = 0.f;
            #pragma unroll
            for (int d = 0; d < HD; ++d) sum = fmaf(qr[d], Ks[kk][d], sum);
            sum += msk[kk];
            s[kk] = sum;
            tmax = fmaxf(tmax, sum);
        }
        const float corr = __expf(mx - tmax);
        l *= corr;
        #pragma unroll
        for (int d = 0; d < HD; ++d) acc[d] *= corr;
        mx = tmax;
        #pragma unroll
        for (int kk = 0; kk < KT; ++kk) {
            const float p = __expf(s[kk] - mx);
            l += p;
            #pragma unroll
            for (int d = 0; d < HD; ++d) acc[d] = fmaf(p, Vs[kk][d], acc[d]);
        }
    }

    const float inv = 1.f / l;
    float* op = out + ((size_t)b * SS + row) * DD + h * HD;
    #pragma unroll
    for (int d = 0; d < HD; ++d) op[d] = acc[d] * inv;
}

// ---------------- Fused residual-add + LayerNorm ---------------------------
// out_row = gamma * normalize(a_row + r_row) + beta, one block per row.
__global__ __launch_bounds__(256)
void ln_kernel(const float* __restrict__ a, const float* __restrict__ r,
               const float* __restrict__ gamma, const float* __restrict__ beta,
               float* __restrict__ out)
{
    const size_t base = (size_t)blockIdx.x * DD;
    const int t = threadIdx.x;

    const float v0 = a[base + t]       + r[base + t];
    const float v1 = a[base + t + 256] + r[base + t + 256];
    const float v2 = a[base + t + 512] + r[base + t + 512];

    float s  = v0 + v1 + v2;
    float ss = v0 * v0 + v1 * v1 + v2 * v2;
    #pragma unroll
    for (int o = 16; o > 0; o >>= 1) {
        s  += __shfl_xor_sync(0xFFFFFFFFu, s,  o);
        ss += __shfl_xor_sync(0xFFFFFFFFu, ss, o);
    }
    __shared__ float rs[8], rss[8], stats[2];
    const int wid = t >> 5, lid = t & 31;
    if (lid == 0) { rs[wid] = s; rss[wid] = ss; }
    __syncthreads();
    if (t == 0) {
        float S = 0.f, SSq = 0.f;
        #pragma unroll
        for (int i = 0; i < 8; ++i) { S += rs[i]; SSq += rss[i]; }
        const float mu  = S * (1.f / DD);
        const float var = SSq * (1.f / DD) - mu * mu;
        stats[0] = mu;
        stats[1] = rsqrtf(var + 1e-12f);
    }
    __syncthreads();
    const float mu = stats[0], rstd = stats[1];

    out[base + t]       = gamma[t]       * (v0 - mu) * rstd + beta[t];
    out[base + t + 256] = gamma[t + 256] * (v1 - mu) * rstd + beta[t + 256];
    out[base + t + 512] = gamma[t + 512] * (v2 - mu) * rstd + beta[t + 512];
}

// ---------------- launcher -------------------------------------------------
extern "C" void kernel_launch(void* const* d_in, const int* in_sizes, int n_in,
                              void* d_out, int out_size)
{
    // metadata order:
    // x, mask, Wq, bq, Wk, bk, Wv, bv, Wp, bp, g1, be1, W1, bf1, W2, bf2, g2, be2
    const float* x    = (const float*)d_in[0];
    const float* mask = (const float*)d_in[1];
    const float* Wq   = (const float*)d_in[2];
    const float* bq   = (const float*)d_in[3];
    const float* Wk   = (const float*)d_in[4];
    const float* bk   = (const float*)d_in[5];
    const float* Wv   = (const float*)d_in[6];
    const float* bv   = (const float*)d_in[7];
    const float* Wp   = (const float*)d_in[8];
    const float* bp   = (const float*)d_in[9];
    const float* g1   = (const float*)d_in[10];
    const float* be1  = (const float*)d_in[11];
    const float* W1   = (const float*)d_in[12];
    const float* bf1  = (const float*)d_in[13];
    const float* W2   = (const float*)d_in[14];
    const float* bf2  = (const float*)d_in[15];
    const float* g2   = (const float*)d_in[16];
    const float* be2  = (const float*)d_in[17];
    float* outp = (float*)d_out;

    float *pq, *pk, *pv, *pattn, *pproj, *px1, *pff, *pff2;
    cudaGetSymbolAddress((void**)&pq,    g_q);
    cudaGetSymbolAddress((void**)&pk,    g_k);
    cudaGetSymbolAddress((void**)&pv,    g_v);
    cudaGetSymbolAddress((void**)&pattn, g_attn);
    cudaGetSymbolAddress((void**)&pproj, g_proj);
    cudaGetSymbolAddress((void**)&px1,   g_x1);
    cudaGetSymbolAddress((void**)&pff,   g_ff);
    cudaGetSymbolAddress((void**)&pff2,  g_ff2);

    const dim3 blk(256);
    const dim3 grid_d(DD / 128, MM / 128);      // (6, 32)
    const dim3 grid_ff1(DFF / 128, MM / 128);   // (24, 32)

    // QKV projections
    sgemm_nt<0><<<grid_d, blk>>>(MM, DD, DD, x, Wq, bq, pq);
    sgemm_nt<0><<<grid_d, blk>>>(MM, DD, DD, x, Wk, bk, pk);
    sgemm_nt<0><<<grid_d, blk>>>(MM, DD, DD, x, Wv, bv, pv);

    // Attention
    attn_kernel<<<dim3(SS / 128, HH, BB), 128>>>(pq, pk, pv, mask, pattn);

    // Output projection + residual + LN1
    sgemm_nt<0><<<grid_d, blk>>>(MM, DD, DD, pattn, Wp, bp, pproj);
    ln_kernel<<<MM, 256>>>(x, pproj, g1, be1, px1);

    // FFN
    sgemm_nt<1><<<grid_ff1, blk>>>(MM, DFF, DD, px1, W1, bf1, pff);   // + exact GELU
    sgemm_nt<0><<<grid_d, blk>>>(MM, DD, DFF, pff, W2, bf2, pff2);

    // Residual + LN2 -> output
    ln_kernel<<<MM, 256>>>(px1, pff2, g2, be2, outp);
}

// round 4
// speedup vs baseline: 1.4814x; 1.4814x over previous
#include <cuda_runtime.h>
#include <cuda_bf16.h>
#include <math.h>
#include <stdint.h>

// Problem dims (fixed by dataset)
#define BB 2
#define SS 2048
#define DD 768
#define HH 12
#define HD 64
#define DFF 3072
#define MM (BB * SS)   // 4096 tokens

// ---------------- scratch (no allocations allowed) ----------------
__device__ __align__(16) float g_q[MM * DD];
__device__ __align__(16) float g_k[MM * DD];
__device__ __align__(16) float g_v[MM * DD];
__device__ __align__(16) float g_attn[MM * DD];
__device__ __align__(16) float g_proj[MM * DD];
__device__ __align__(16) float g_x1[MM * DD];
__device__ __align__(16) float g_ff[MM * DFF];
__device__ __align__(16) float g_ff2[MM * DD];

// ---------------- helpers --------------------------------------------------
__device__ __forceinline__ uint32_t f2tf(float f) {
    uint32_t r;
    asm("cvt.rna.tf32.f32 %0, %1;" : "=r"(r) : "f"(f));
    return r;
}

__device__ __forceinline__ void mma_tf32(float* c, const uint32_t* a, const uint32_t* b) {
    asm volatile(
        "mma.sync.aligned.m16n8k8.row.col.f32.tf32.tf32.f32 "
        "{%0,%1,%2,%3},{%4,%5,%6,%7},{%8,%9},{%0,%1,%2,%3};\n"
        : "+f"(c[0]), "+f"(c[1]), "+f"(c[2]), "+f"(c[3])
        : "r"(a[0]), "r"(a[1]), "r"(a[2]), "r"(a[3]), "r"(b[0]), "r"(b[1]));
}

// ---------------- TF32 tensor-core GEMM ------------------------------------
// C[M,N] = A[M,K] @ W[N,K]^T + bias (+gelu).  BM=BN=128, BK=16.
// 256 threads = 8 warps, each warp computes 64x32 via 4x4 m16n8k8 tiles.
// blockIdx.z selects among up to 3 (W,bias,C) triples sharing the same A
// (used to batch Q/K/V into one launch for better wave packing).
template<int GELU>
__global__ __launch_bounds__(256)
void gemm_tf32(int K, int N, const float* __restrict__ A,
               const float* __restrict__ W0, const float* __restrict__ bia0, float* __restrict__ C0,
               const float* __restrict__ W1, const float* __restrict__ bia1, float* __restrict__ C1,
               const float* __restrict__ W2, const float* __restrict__ bia2, float* __restrict__ C2)
{
    // stride 20 words avoids LDS bank conflicts on the fragment reads
    __shared__ uint32_t As[2][128][20];
    __shared__ uint32_t Bs[2][128][20];

    const int z = blockIdx.z;
    const float* W   = (z == 0) ? W0   : (z == 1) ? W1   : W2;
    const float* bia = (z == 0) ? bia0 : (z == 1) ? bia1 : bia2;
    float*       C   = (z == 0) ? C0   : (z == 1) ? C1   : C2;

    const int tid  = threadIdx.x;
    const int lane = tid & 31;
    const int wid  = tid >> 5;
    const int wm   = (wid >> 2) * 64;   // warp M offset: 0 / 64
    const int wn   = (wid & 3) * 32;    // warp N offset: 0/32/64/96
    const int l4   = lane >> 2;
    const int lm   = lane & 3;

    const float* Ag = A + (size_t)blockIdx.y * 128 * K;
    const float* Wg = W + (size_t)blockIdx.x * 128 * K;

    // global->smem staging mapping: 512 float4 per 128x16 tile, 2 per thread
    const int f0 = tid,       r0 = f0 >> 2, c0 = (f0 & 3) << 2;
    const int f1 = tid + 256, r1 = f1 >> 2, c1 = (f1 & 3) << 2;

    float acc[4][4][4];
    #pragma unroll
    for (int i = 0; i < 4; ++i)
        #pragma unroll
        for (int j = 0; j < 4; ++j)
            #pragma unroll
            for (int r = 0; r < 4; ++r) acc[i][j][r] = 0.f;

    float4 sa0, sa1, sb0, sb1;

    auto load_tile = [&](int k0) {
        sa0 = *reinterpret_cast<const float4*>(Ag + (size_t)r0 * K + k0 + c0);
        sa1 = *reinterpret_cast<const float4*>(Ag + (size_t)r1 * K + k0 + c1);
        sb0 = *reinterpret_cast<const float4*>(Wg + (size_t)r0 * K + k0 + c0);
        sb1 = *reinterpret_cast<const float4*>(Wg + (size_t)r1 * K + k0 + c1);
    };
    auto store_tile = [&](int bf) {
        *reinterpret_cast<uint4*>(&As[bf][r0][c0]) =
            make_uint4(f2tf(sa0.x), f2tf(sa0.y), f2tf(sa0.z), f2tf(sa0.w));
        *reinterpret_cast<uint4*>(&As[bf][r1][c1]) =
            make_uint4(f2tf(sa1.x), f2tf(sa1.y), f2tf(sa1.z), f2tf(sa1.w));
        *reinterpret_cast<uint4*>(&Bs[bf][r0][c0]) =
            make_uint4(f2tf(sb0.x), f2tf(sb0.y), f2tf(sb0.z), f2tf(sb0.w));
        *reinterpret_cast<uint4*>(&Bs[bf][r1][c1]) =
            make_uint4(f2tf(sb1.x), f2tf(sb1.y), f2tf(sb1.z), f2tf(sb1.w));
    };
    auto compute = [&](int bf) {
        #pragma unroll
        for (int ks = 0; ks < 16; ks += 8) {
            uint32_t af[4][4], bfrag[4][2];
            #pragma unroll
            for (int i = 0; i < 4; ++i) {
                const int mr = wm + i * 16 + l4;
                af[i][0] = As[bf][mr][ks + lm];
                af[i][1] = As[bf][mr + 8][ks + lm];
                af[i][2] = As[bf][mr][ks + lm + 4];
                af[i][3] = As[bf][mr + 8][ks + lm + 4];
            }
            #pragma unroll
            for (int j = 0; j < 4; ++j) {
                const int nr = wn + j * 8 + l4;
                bfrag[j][0] = Bs[bf][nr][ks + lm];
                bfrag[j][1] = Bs[bf][nr][ks + lm + 4];
            }
            #pragma unroll
            for (int i = 0; i < 4; ++i)
                #pragma unroll
                for (int j = 0; j < 4; ++j)
                    mma_tf32(acc[i][j], af[i], bfrag[j]);
        }
    };

    load_tile(0);
    store_tile(0);
    __syncthreads();

    int buf = 0;
    for (int k0 = 16; k0 < K; k0 += 16) {
        load_tile(k0);          // prefetch next tile into regs
        compute(buf);           // compute current tile
        store_tile(buf ^ 1);    // stage next tile
        __syncthreads();
        buf ^= 1;
    }
    compute(buf);

    // epilogue: bias (+gelu), float2 stores
    #pragma unroll
    for (int i = 0; i < 4; ++i) {
        const int row = blockIdx.y * 128 + wm + i * 16 + l4;
        #pragma unroll
        for (int j = 0; j < 4; ++j) {
            const int col = blockIdx.x * 128 + wn + j * 8 + lm * 2;
            const float bv0 = bia[col], bv1 = bia[col + 1];
            float v0 = acc[i][j][0] + bv0;
            float v1 = acc[i][j][1] + bv1;
            float v2 = acc[i][j][2] + bv0;
            float v3 = acc[i][j][3] + bv1;
            if (GELU) {
                v0 = 0.5f * v0 * (1.f + erff(v0 * 0.70710678118654752f));
                v1 = 0.5f * v1 * (1.f + erff(v1 * 0.70710678118654752f));
                v2 = 0.5f * v2 * (1.f + erff(v2 * 0.70710678118654752f));
                v3 = 0.5f * v3 * (1.f + erff(v3 * 0.70710678118654752f));
            }
            *reinterpret_cast<float2*>(C + (size_t)row * N + col)       = make_float2(v0, v1);
            *reinterpret_cast<float2*>(C + (size_t)(row + 8) * N + col) = make_float2(v2, v3);
        }
    }
}

// ---------------- Attention: flash-style, quad (4 threads) per query -------
// Each thread of a quad owns 16 of the 64 head dims (interleaved 4-float
// slices for conflict-free smem access). Score reduced with 2 shfl_xor.
__global__ __launch_bounds__(128)
void attn_quad(const float* __restrict__ q,
               const float* __restrict__ k,
               const float* __restrict__ v,
               const float* __restrict__ mask,
               float* __restrict__ out)
{
    constexpr int KT = 32;
    __shared__ float Ks[KT][HD];
    __shared__ float Vs[KT][HD];
    __shared__ float msk[KT];

    const int b   = blockIdx.z;
    const int h   = blockIdx.y;
    const int tid = threadIdx.x;
    const int lm  = tid & 3;                       // quad lane
    const int qi  = blockIdx.x * 32 + (tid >> 2);  // query row

    const size_t qofs = ((size_t)b * SS + qi) * DD + h * HD;

    float4 q4[4];
    #pragma unroll
    for (int j = 0; j < 4; ++j) {
        float4 t = *reinterpret_cast<const float4*>(q + qofs + lm * 4 + 16 * j);
        q4[j] = make_float4(t.x * 0.125f, t.y * 0.125f, t.z * 0.125f, t.w * 0.125f);
    }
    float4 a4[4];
    #pragma unroll
    for (int j = 0; j < 4; ++j) a4[j] = make_float4(0.f, 0.f, 0.f, 0.f);
    float mx = -1e30f, l = 0.f;

    for (int kt = 0; kt < SS; kt += KT) {
        __syncthreads();
        #pragma unroll
        for (int i = 0; i < 4; ++i) {
            const int f = i * 128 + tid;
            const int r = f >> 4, c = (f & 15) << 2;
            const size_t g = ((size_t)b * SS + kt + r) * DD + h * HD + c;
            *reinterpret_cast<float4*>(&Ks[r][c]) = *reinterpret_cast<const float4*>(k + g);
            *reinterpret_cast<float4*>(&Vs[r][c]) = *reinterpret_cast<const float4*>(v + g);
        }
        if (tid < KT) msk[tid] = -10000.f * (1.f - mask[(size_t)b * SS + kt + tid]);
        __syncthreads();

        float s[KT];
        float tmax = mx;
        #pragma unroll
        for (int kk = 0; kk < KT; ++kk) {
            float p = 0.f;
            #pragma unroll
            for (int j = 0; j < 4; ++j) {
                const float4 kv = *reinterpret_cast<const float4*>(&Ks[kk][lm * 4 + 16 * j]);
                p = fmaf(q4[j].x, kv.x, p);
                p = fmaf(q4[j].y, kv.y, p);
                p = fmaf(q4[j].z, kv.z, p);
                p = fmaf(q4[j].w, kv.w, p);
            }
            p += __shfl_xor_sync(0xFFFFFFFFu, p, 1);
            p += __shfl_xor_sync(0xFFFFFFFFu, p, 2);
            p += msk[kk];
            s[kk] = p;
            tmax = fmaxf(tmax, p);
        }
        const float corr = __expf(mx - tmax);
        l *= corr;
        #pragma unroll
        for (int j = 0; j < 4; ++j) {
            a4[j].x *= corr; a4[j].y *= corr; a4[j].z *= corr; a4[j].w *= corr;
        }
        mx = tmax;
        #pragma unroll
        for (int kk = 0; kk < KT; ++kk) {
            const float p = __expf(s[kk] - mx);
            l += p;
            #pragma unroll
            for (int j = 0; j < 4; ++j) {
                const float4 vv = *reinterpret_cast<const float4*>(&Vs[kk][lm * 4 + 16 * j]);
                a4[j].x = fmaf(p, vv.x, a4[j].x);
                a4[j].y = fmaf(p, vv.y, a4[j].y);
                a4[j].z = fmaf(p, vv.z, a4[j].z);
                a4[j].w = fmaf(p, vv.w, a4[j].w);
            }
        }
    }

    const float inv = 1.f / l;
    #pragma unroll
    for (int j = 0; j < 4; ++j) {
        *reinterpret_cast<float4*>(out + qofs + lm * 4 + 16 * j) =
            make_float4(a4[j].x * inv, a4[j].y * inv, a4[j].z * inv, a4[j].w * inv);
    }
}

// ---------------- Fused residual-add + LayerNorm ---------------------------
__global__ __launch_bounds__(256)
void ln_kernel(const float* __restrict__ a, const float* __restrict__ r,
               const float* __restrict__ gamma, const float* __restrict__ beta,
               float* __restrict__ out)
{
    const size_t base = (size_t)blockIdx.x * DD;
    const int t = threadIdx.x;

    const float v0 = a[base + t]       + r[base + t];
    const float v1 = a[base + t + 256] + r[base + t + 256];
    const float v2 = a[base + t + 512] + r[base + t + 512];

    float s  = v0 + v1 + v2;
    float ss = v0 * v0 + v1 * v1 + v2 * v2;
    #pragma unroll
    for (int o = 16; o > 0; o >>= 1) {
        s  += __shfl_xor_sync(0xFFFFFFFFu, s,  o);
        ss += __shfl_xor_sync(0xFFFFFFFFu, ss, o);
    }
    __shared__ float rs[8], rss[8], stats[2];
    const int wid = t >> 5, lid = t & 31;
    if (lid == 0) { rs[wid] = s; rss[wid] = ss; }
    __syncthreads();
    if (t == 0) {
        float S = 0.f, SSq = 0.f;
        #pragma unroll
        for (int i = 0; i < 8; ++i) { S += rs[i]; SSq += rss[i]; }
        const float mu  = S * (1.f / DD);
        const float var = SSq * (1.f / DD) - mu * mu;
        stats[0] = mu;
        stats[1] = rsqrtf(var + 1e-12f);
    }
    __syncthreads();
    const float mu = stats[0], rstd = stats[1];

    out[base + t]       = gamma[t]       * (v0 - mu) * rstd + beta[t];
    out[base + t + 256] = gamma[t + 256] * (v1 - mu) * rstd + beta[t + 256];
    out[base + t + 512] = gamma[t + 512] * (v2 - mu) * rstd + beta[t + 512];
}

// ---------------- launcher -------------------------------------------------
extern "C" void kernel_launch(void* const* d_in, const int* in_sizes, int n_in,
                              void* d_out, int out_size)
{
    const float* x    = (const float*)d_in[0];
    const float* mask = (const float*)d_in[1];
    const float* Wq   = (const float*)d_in[2];
    const float* bq   = (const float*)d_in[3];
    const float* Wk   = (const float*)d_in[4];
    const float* bk   = (const float*)d_in[5];
    const float* Wv   = (const float*)d_in[6];
    const float* bv   = (const float*)d_in[7];
    const float* Wp   = (const float*)d_in[8];
    const float* bp   = (const float*)d_in[9];
    const float* g1   = (const float*)d_in[10];
    const float* be1  = (const float*)d_in[11];
    const float* W1   = (const float*)d_in[12];
    const float* bf1  = (const float*)d_in[13];
    const float* W2   = (const float*)d_in[14];
    const float* bf2  = (const float*)d_in[15];
    const float* g2   = (const float*)d_in[16];
    const float* be2  = (const float*)d_in[17];
    float* outp = (float*)d_out;

    float *pq, *pk, *pv, *pattn, *pproj, *px1, *pff, *pff2;
    cudaGetSymbolAddress((void**)&pq,    g_q);
    cudaGetSymbolAddress((void**)&pk,    g_k);
    cudaGetSymbolAddress((void**)&pv,    g_v);
    cudaGetSymbolAddress((void**)&pattn, g_attn);
    cudaGetSymbolAddress((void**)&pproj, g_proj);
    cudaGetSymbolAddress((void**)&px1,   g_x1);
    cudaGetSymbolAddress((void**)&pff,   g_ff);
    cudaGetSymbolAddress((void**)&pff2,  g_ff2);

    const dim3 blk(256);

    // QKV projections: one launch, z selects W/bias/out (576 blocks)
    gemm_tf32<0><<<dim3(DD / 128, MM / 128, 3), blk>>>(
        DD, DD, x, Wq, bq, pq, Wk, bk, pk, Wv, bv, pv);

    // Attention
    attn_quad<<<dim3(SS / 32, HH, BB), 128>>>(pq, pk, pv, mask, pattn);

    // Output projection + residual + LN1
    gemm_tf32<0><<<dim3(DD / 128, MM / 128, 1), blk>>>(
        DD, DD, pattn, Wp, bp, pproj, Wp, bp, pproj, Wp, bp, pproj);
    ln_kernel<<<MM, 256>>>(x, pproj, g1, be1, px1);

    // FFN
    gemm_tf32<1><<<dim3(DFF / 128, MM / 128, 1), blk>>>(
        DD, DFF, px1, W1, bf1, pff, W1, bf1, pff, W1, bf1, pff);
    gemm_tf32<0><<<dim3(DD / 128, MM / 128, 1), blk>>>(
        DFF, DD, pff, W2, bf2, pff2, W2, bf2, pff2, W2, bf2, pff2);

    // Residual + LN2 -> output
    ln_kernel<<<MM, 256>>>(px1, pff2, g2, be2, outp);
}

// round 5
// speedup vs baseline: 3.7585x; 2.5371x over previous
#include <cuda_runtime.h>
#include <cuda_bf16.h>
#include <math.h>
#include <stdint.h>

// Problem dims (fixed by dataset)
#define BB 2
#define SS 2048
#define DD 768
#define HH 12
#define HD 64
#define DFF 3072
#define MM (BB * SS)   // 4096 tokens

// ---------------- scratch (no allocations allowed) ----------------
__device__ __align__(16) float g_q[MM * DD];
__device__ __align__(16) float g_k[MM * DD];
__device__ __align__(16) float g_v[MM * DD];
__device__ __align__(16) float g_attn[MM * DD];
__device__ __align__(16) float g_proj[MM * DD];
__device__ __align__(16) float g_x1[MM * DD];
__device__ __align__(16) float g_ff[MM * DFF];
__device__ __align__(16) float g_ff2[MM * DD];

// ---------------- helpers --------------------------------------------------
__device__ __forceinline__ uint32_t f2tf(float f) {
    uint32_t r;
    asm("cvt.rna.tf32.f32 %0, %1;" : "=r"(r) : "f"(f));
    return r;
}

__device__ __forceinline__ void mma_tf32(float* c, const uint32_t* a, const uint32_t* b) {
    asm volatile(
        "mma.sync.aligned.m16n8k8.row.col.f32.tf32.tf32.f32 "
        "{%0,%1,%2,%3},{%4,%5,%6,%7},{%8,%9},{%0,%1,%2,%3};\n"
        : "+f"(c[0]), "+f"(c[1]), "+f"(c[2]), "+f"(c[3])
        : "r"(a[0]), "r"(a[1]), "r"(a[2]), "r"(a[3]), "r"(b[0]), "r"(b[1]));
}

// ---------------- TF32 tensor-core GEMM ------------------------------------
// C[M,N] = A[M,K] @ W[N,K]^T + bias (+gelu).  BM in {64,128}, BN=128, BK=16.
// 256 threads = 8 warps; warp tile = (BM/2) x 32 via (BM/32)x4 m16n8k8 tiles.
// blockIdx.z selects among up to 3 (W,bias,C) triples sharing the same A.
template<int GELU, int BM>
__global__ __launch_bounds__(256)
void gemm_tf32(int K, int N, const float* __restrict__ A,
               const float* __restrict__ W0, const float* __restrict__ bia0, float* __restrict__ C0,
               const float* __restrict__ W1, const float* __restrict__ bia1, float* __restrict__ C1,
               const float* __restrict__ W2, const float* __restrict__ bia2, float* __restrict__ C2)
{
    constexpr int MI = BM / 32;          // i-tiles per warp
    __shared__ uint32_t As[2][BM][20];   // stride 20: conflict-free frag reads
    __shared__ uint32_t Bs[2][128][20];

    const int z = blockIdx.z;
    const float* W   = (z == 0) ? W0   : (z == 1) ? W1   : W2;
    const float* bia = (z == 0) ? bia0 : (z == 1) ? bia1 : bia2;
    float*       C   = (z == 0) ? C0   : (z == 1) ? C1   : C2;

    const int tid  = threadIdx.x;
    const int lane = tid & 31;
    const int wid  = tid >> 5;
    const int wm   = (wid >> 2) * (BM / 2);
    const int wn   = (wid & 3) * 32;
    const int l4   = lane >> 2;
    const int lm   = lane & 3;

    const float* Ag = A + (size_t)blockIdx.y * BM * K;
    const float* Wg = W + (size_t)blockIdx.x * 128 * K;

    const int r0 = tid >> 2,          c0 = (tid & 3) << 2;
    const int r1 = (tid + 256) >> 2,  c1 = (tid & 3) << 2;   // second B chunk / A chunk (BM=128)

    float acc[MI][4][4];
    #pragma unroll
    for (int i = 0; i < MI; ++i)
        #pragma unroll
        for (int j = 0; j < 4; ++j)
            #pragma unroll
            for (int r = 0; r < 4; ++r) acc[i][j][r] = 0.f;

    float4 sa0, sa1, sb0, sb1;

    auto load_tile = [&](int k0) {
        sa0 = *reinterpret_cast<const float4*>(Ag + (size_t)r0 * K + k0 + c0);
        if (BM == 128)
            sa1 = *reinterpret_cast<const float4*>(Ag + (size_t)r1 * K + k0 + c1);
        sb0 = *reinterpret_cast<const float4*>(Wg + (size_t)r0 * K + k0 + c0);
        sb1 = *reinterpret_cast<const float4*>(Wg + (size_t)r1 * K + k0 + c1);
    };
    auto store_tile = [&](int bf) {
        *reinterpret_cast<uint4*>(&As[bf][r0][c0]) =
            make_uint4(f2tf(sa0.x), f2tf(sa0.y), f2tf(sa0.z), f2tf(sa0.w));
        if (BM == 128)
            *reinterpret_cast<uint4*>(&As[bf][r1][c1]) =
                make_uint4(f2tf(sa1.x), f2tf(sa1.y), f2tf(sa1.z), f2tf(sa1.w));
        *reinterpret_cast<uint4*>(&Bs[bf][r0][c0]) =
            make_uint4(f2tf(sb0.x), f2tf(sb0.y), f2tf(sb0.z), f2tf(sb0.w));
        *reinterpret_cast<uint4*>(&Bs[bf][r1][c1]) =
            make_uint4(f2tf(sb1.x), f2tf(sb1.y), f2tf(sb1.z), f2tf(sb1.w));
    };
    auto compute = [&](int bf) {
        #pragma unroll
        for (int ks = 0; ks < 16; ks += 8) {
            uint32_t af[MI][4], bfrag[4][2];
            #pragma unroll
            for (int i = 0; i < MI; ++i) {
                const int mr = wm + i * 16 + l4;
                af[i][0] = As[bf][mr][ks + lm];
                af[i][1] = As[bf][mr + 8][ks + lm];
                af[i][2] = As[bf][mr][ks + lm + 4];
                af[i][3] = As[bf][mr + 8][ks + lm + 4];
            }
            #pragma unroll
            for (int j = 0; j < 4; ++j) {
                const int nr = wn + j * 8 + l4;
                bfrag[j][0] = Bs[bf][nr][ks + lm];
                bfrag[j][1] = Bs[bf][nr][ks + lm + 4];
            }
            #pragma unroll
            for (int i = 0; i < MI; ++i)
                #pragma unroll
                for (int j = 0; j < 4; ++j)
                    mma_tf32(acc[i][j], af[i], bfrag[j]);
        }
    };

    load_tile(0);
    store_tile(0);
    __syncthreads();

    int buf = 0;
    for (int k0 = 16; k0 < K; k0 += 16) {
        load_tile(k0);
        compute(buf);
        store_tile(buf ^ 1);
        __syncthreads();
        buf ^= 1;
    }
    compute(buf);

    #pragma unroll
    for (int i = 0; i < MI; ++i) {
        const int row = blockIdx.y * BM + wm + i * 16 + l4;
        #pragma unroll
        for (int j = 0; j < 4; ++j) {
            const int col = blockIdx.x * 128 + wn + j * 8 + lm * 2;
            const float bv0 = bia[col], bv1 = bia[col + 1];
            float v0 = acc[i][j][0] + bv0;
            float v1 = acc[i][j][1] + bv1;
            float v2 = acc[i][j][2] + bv0;
            float v3 = acc[i][j][3] + bv1;
            if (GELU) {
                v0 = 0.5f * v0 * (1.f + erff(v0 * 0.70710678118654752f));
                v1 = 0.5f * v1 * (1.f + erff(v1 * 0.70710678118654752f));
                v2 = 0.5f * v2 * (1.f + erff(v2 * 0.70710678118654752f));
                v3 = 0.5f * v3 * (1.f + erff(v3 * 0.70710678118654752f));
            }
            *reinterpret_cast<float2*>(C + (size_t)row * N + col)       = make_float2(v0, v1);
            *reinterpret_cast<float2*>(C + (size_t)(row + 8) * N + col) = make_float2(v2, v3);
        }
    }
}

// ---------------- Attention: flash-style with tf32 MMA ---------------------
// 64 queries per block, 4 warps (16 q each), 64-key tiles.
// smem (dynamic, 53504 B): Ks[64][68], Vs[64][72], Ps[64][68] (uint32 tf32), msk[64]
#define ATTN_SMEM 53504
__global__ __launch_bounds__(128)
void attn_mma(const float* __restrict__ q,
              const float* __restrict__ k,
              const float* __restrict__ v,
              const float* __restrict__ mask,
              float* __restrict__ out)
{
    extern __shared__ uint32_t smw[];
    uint32_t (*Ks)[68] = (uint32_t(*)[68])smw;                 // 4352 words
    uint32_t (*Vs)[72] = (uint32_t(*)[72])(smw + 4352);        // 4608 words
    uint32_t (*Ps)[68] = (uint32_t(*)[68])(smw + 4352 + 4608); // 4352 words
    float*    msk      = (float*)(smw + 4352 + 4608 + 4352);   // 64 words

    const int b    = blockIdx.z;
    const int h    = blockIdx.y;
    const int q0   = blockIdx.x * 64;
    const int tid  = threadIdx.x;
    const int w    = tid >> 5;
    const int lane = tid & 31;
    const int g    = lane >> 2;   // group row (0..7)
    const int tg   = lane & 3;    // thread-in-group (cols)

    const size_t boff = (size_t)b * SS;
    const int hofs = h * HD;
    const int rlo = q0 + w * 16 + g;     // low row of this thread
    const int prow = w * 16 + g;         // Ps row (per-warp region)

    // Q fragments (pre-scaled by 1/sqrt(HD)), held in registers all kernel
    uint32_t qa[8][4];
    {
        const float* qlo = q + (boff + rlo) * DD + hofs;
        const float* qhi = qlo + 8 * DD;
        #pragma unroll
        for (int ks = 0; ks < 8; ++ks) {
            qa[ks][0] = f2tf(0.125f * qlo[ks * 8 + tg]);
            qa[ks][1] = f2tf(0.125f * qhi[ks * 8 + tg]);
            qa[ks][2] = f2tf(0.125f * qlo[ks * 8 + tg + 4]);
            qa[ks][3] = f2tf(0.125f * qhi[ks * 8 + tg + 4]);
        }
    }

    float o[8][4];
    #pragma unroll
    for (int j = 0; j < 8; ++j)
        #pragma unroll
        for (int r = 0; r < 4; ++r) o[j][r] = 0.f;
    float mx_lo = -1e30f, mx_hi = -1e30f, l_lo = 0.f, l_hi = 0.f;

    for (int kt = 0; kt < SS; kt += 64) {
        __syncthreads();
        // stage K (tf32) and V (tf32) tiles: 64x64 each, 8 float4/thread each
        #pragma unroll
        for (int it = 0; it < 8; ++it) {
            const int idx = it * 128 + tid;
            const int r = idx >> 4, c = (idx & 15) << 2;
            const float4 kv = *reinterpret_cast<const float4*>(
                k + (boff + kt + r) * DD + hofs + c);
            const float4 vv = *reinterpret_cast<const float4*>(
                v + (boff + kt + r) * DD + hofs + c);
            *reinterpret_cast<uint4*>(&Ks[r][c]) =
                make_uint4(f2tf(kv.x), f2tf(kv.y), f2tf(kv.z), f2tf(kv.w));
            *reinterpret_cast<uint4*>(&Vs[r][c]) =
                make_uint4(f2tf(vv.x), f2tf(vv.y), f2tf(vv.z), f2tf(vv.w));
        }
        if (tid < 64) msk[tid] = -10000.f * (1.f - mask[boff + kt + tid]);
        __syncthreads();

        // ---- scores: S[16q x 64k] per warp ----
        float sc[8][4];
        #pragma unroll
        for (int j = 0; j < 8; ++j) {
            sc[j][0] = sc[j][1] = sc[j][2] = sc[j][3] = 0.f;
            #pragma unroll
            for (int ks = 0; ks < 8; ++ks) {
                uint32_t bb[2];
                bb[0] = Ks[j * 8 + g][ks * 8 + tg];
                bb[1] = Ks[j * 8 + g][ks * 8 + tg + 4];
                mma_tf32(sc[j], qa[ks], bb);
            }
        }

        // ---- online softmax ----
        float nm_lo = mx_lo, nm_hi = mx_hi;
        #pragma unroll
        for (int j = 0; j < 8; ++j) {
            const float m0 = msk[j * 8 + 2 * tg], m1 = msk[j * 8 + 2 * tg + 1];
            sc[j][0] += m0; sc[j][1] += m1; sc[j][2] += m0; sc[j][3] += m1;
            nm_lo = fmaxf(nm_lo, fmaxf(sc[j][0], sc[j][1]));
            nm_hi = fmaxf(nm_hi, fmaxf(sc[j][2], sc[j][3]));
        }
        nm_lo = fmaxf(nm_lo, __shfl_xor_sync(0xFFFFFFFFu, nm_lo, 1));
        nm_lo = fmaxf(nm_lo, __shfl_xor_sync(0xFFFFFFFFu, nm_lo, 2));
        nm_hi = fmaxf(nm_hi, __shfl_xor_sync(0xFFFFFFFFu, nm_hi, 1));
        nm_hi = fmaxf(nm_hi, __shfl_xor_sync(0xFFFFFFFFu, nm_hi, 2));
        const float cor_lo = __expf(mx_lo - nm_lo);
        const float cor_hi = __expf(mx_hi - nm_hi);
        mx_lo = nm_lo; mx_hi = nm_hi;

        float sl_lo = 0.f, sl_hi = 0.f;
        #pragma unroll
        for (int j = 0; j < 8; ++j) {
            const float p0 = __expf(sc[j][0] - mx_lo);
            const float p1 = __expf(sc[j][1] - mx_lo);
            const float p2 = __expf(sc[j][2] - mx_hi);
            const float p3 = __expf(sc[j][3] - mx_hi);
            sl_lo += p0 + p1; sl_hi += p2 + p3;
            *reinterpret_cast<uint2*>(&Ps[prow][j * 8 + 2 * tg]) =
                make_uint2(f2tf(p0), f2tf(p1));
            *reinterpret_cast<uint2*>(&Ps[prow + 8][j * 8 + 2 * tg]) =
                make_uint2(f2tf(p2), f2tf(p3));
            o[j][0] *= cor_lo; o[j][1] *= cor_lo;
            o[j][2] *= cor_hi; o[j][3] *= cor_hi;
        }
        sl_lo += __shfl_xor_sync(0xFFFFFFFFu, sl_lo, 1);
        sl_lo += __shfl_xor_sync(0xFFFFFFFFu, sl_lo, 2);
        sl_hi += __shfl_xor_sync(0xFFFFFFFFu, sl_hi, 1);
        sl_hi += __shfl_xor_sync(0xFFFFFFFFu, sl_hi, 2);
        l_lo = l_lo * cor_lo + sl_lo;
        l_hi = l_hi * cor_hi + sl_hi;
        __syncwarp();

        // ---- PV: O += P[16 x 64] * V[64 x 64] ----
        #pragma unroll
        for (int ks = 0; ks < 8; ++ks) {
            uint32_t a[4];
            a[0] = Ps[w * 16 + g][ks * 8 + tg];
            a[1] = Ps[w * 16 + g + 8][ks * 8 + tg];
            a[2] = Ps[w * 16 + g][ks * 8 + tg + 4];
            a[3] = Ps[w * 16 + g + 8][ks * 8 + tg + 4];
            #pragma unroll
            for (int j = 0; j < 8; ++j) {
                uint32_t bb[2];
                bb[0] = Vs[ks * 8 + tg][j * 8 + g];
                bb[1] = Vs[ks * 8 + tg + 4][j * 8 + g];
                mma_tf32(o[j], a, bb);
            }
        }
        __syncwarp();
    }

    const float inv_lo = 1.f / l_lo;
    const float inv_hi = 1.f / l_hi;
    float* olo = out + (boff + rlo) * DD + hofs;
    float* ohi = olo + 8 * DD;
    #pragma unroll
    for (int j = 0; j < 8; ++j) {
        *reinterpret_cast<float2*>(olo + j * 8 + 2 * tg) =
            make_float2(o[j][0] * inv_lo, o[j][1] * inv_lo);
        *reinterpret_cast<float2*>(ohi + j * 8 + 2 * tg) =
            make_float2(o[j][2] * inv_hi, o[j][3] * inv_hi);
    }
}

// ---------------- Fused residual-add + LayerNorm ---------------------------
__global__ __launch_bounds__(256)
void ln_kernel(const float* __restrict__ a, const float* __restrict__ r,
               const float* __restrict__ gamma, const float* __restrict__ beta,
               float* __restrict__ out)
{
    const size_t base = (size_t)blockIdx.x * DD;
    const int t = threadIdx.x;

    const float v0 = a[base + t]       + r[base + t];
    const float v1 = a[base + t + 256] + r[base + t + 256];
    const float v2 = a[base + t + 512] + r[base + t + 512];

    float s  = v0 + v1 + v2;
    float ss = v0 * v0 + v1 * v1 + v2 * v2;
    #pragma unroll
    for (int o = 16; o > 0; o >>= 1) {
        s  += __shfl_xor_sync(0xFFFFFFFFu, s,  o);
        ss += __shfl_xor_sync(0xFFFFFFFFu, ss, o);
    }
    __shared__ float rs[8], rss[8], stats[2];
    const int wid = t >> 5, lid = t & 31;
    if (lid == 0) { rs[wid] = s; rss[wid] = ss; }
    __syncthreads();
    if (t == 0) {
        float S = 0.f, SSq = 0.f;
        #pragma unroll
        for (int i = 0; i < 8; ++i) { S += rs[i]; SSq += rss[i]; }
        const float mu  = S * (1.f / DD);
        const float var = SSq * (1.f / DD) - mu * mu;
        stats[0] = mu;
        stats[1] = rsqrtf(var + 1e-12f);
    }
    __syncthreads();
    const float mu = stats[0], rstd = stats[1];

    out[base + t]       = gamma[t]       * (v0 - mu) * rstd + beta[t];
    out[base + t + 256] = gamma[t + 256] * (v1 - mu) * rstd + beta[t + 256];
    out[base + t + 512] = gamma[t + 512] * (v2 - mu) * rstd + beta[t + 512];
}

// ---------------- launcher -------------------------------------------------
extern "C" void kernel_launch(void* const* d_in, const int* in_sizes, int n_in,
                              void* d_out, int out_size)
{
    const float* x    = (const float*)d_in[0];
    const float* mask = (const float*)d_in[1];
    const float* Wq   = (const float*)d_in[2];
    const float* bq   = (const float*)d_in[3];
    const float* Wk   = (const float*)d_in[4];
    const float* bk   = (const float*)d_in[5];
    const float* Wv   = (const float*)d_in[6];
    const float* bv   = (const float*)d_in[7];
    const float* Wp   = (const float*)d_in[8];
    const float* bp   = (const float*)d_in[9];
    const float* g1   = (const float*)d_in[10];
    const float* be1  = (const float*)d_in[11];
    const float* W1   = (const float*)d_in[12];
    const float* bf1  = (const float*)d_in[13];
    const float* W2   = (const float*)d_in[14];
    const float* bf2  = (const float*)d_in[15];
    const float* g2   = (const float*)d_in[16];
    const float* be2  = (const float*)d_in[17];
    float* outp = (float*)d_out;

    float *pq, *pk, *pv, *pattn, *pproj, *px1, *pff, *pff2;
    cudaGetSymbolAddress((void**)&pq,    g_q);
    cudaGetSymbolAddress((void**)&pk,    g_k);
    cudaGetSymbolAddress((void**)&pv,    g_v);
    cudaGetSymbolAddress((void**)&pattn, g_attn);
    cudaGetSymbolAddress((void**)&pproj, g_proj);
    cudaGetSymbolAddress((void**)&px1,   g_x1);
    cudaGetSymbolAddress((void**)&pff,   g_ff);
    cudaGetSymbolAddress((void**)&pff2,  g_ff2);

    cudaFuncSetAttribute(attn_mma, cudaFuncAttributeMaxDynamicSharedMemorySize, ATTN_SMEM);

    const dim3 blk(256);

    // QKV projections: one launch, z selects W/bias/out (576 blocks)
    gemm_tf32<0, 128><<<dim3(DD / 128, MM / 128, 3), blk>>>(
        DD, DD, x, Wq, bq, pq, Wk, bk, pk, Wv, bv, pv);

    // Attention (tensor-core flash)
    attn_mma<<<dim3(SS / 64, HH, BB), 128, ATTN_SMEM>>>(pq, pk, pv, mask, pattn);

    // Output projection (BM=64 -> 384 blocks) + residual + LN1
    gemm_tf32<0, 64><<<dim3(DD / 128, MM / 64, 1), blk>>>(
        DD, DD, pattn, Wp, bp, pproj, Wp, bp, pproj, Wp, bp, pproj);
    ln_kernel<<<MM, 256>>>(x, pproj, g1, be1, px1);

    // FFN
    gemm_tf32<1, 128><<<dim3(DFF / 128, MM / 128, 1), blk>>>(
        DD, DFF, px1, W1, bf1, pff, W1, bf1, pff, W1, bf1, pff);
    gemm_tf32<0, 64><<<dim3(DD / 128, MM / 64, 1), blk>>>(
        DFF, DD, pff, W2, bf2, pff2, W2, bf2, pff2, W2, bf2, pff2);

    // Residual + LN2 -> output
    ln_kernel<<<MM, 256>>>(px1, pff2, g2, be2, outp);
}

// round 6
// speedup vs baseline: 5.2594x; 1.3993x over previous
#include <cuda_runtime.h>
#include <cuda_bf16.h>
#include <cuda_fp16.h>
#include <math.h>
#include <stdint.h>

// Problem dims (fixed by dataset)
#define BB 2
#define SS 2048
#define DD 768
#define HH 12
#define HD 64
#define DFF 3072
#define MM (BB * SS)   // 4096 tokens

// ---------------- scratch (no allocations allowed) ----------------
__device__ __align__(16) float g_q[MM * DD];
__device__ __align__(16) float g_k[MM * DD];
__device__ __align__(16) float g_v[MM * DD];
__device__ __align__(16) float g_attn[MM * DD];
__device__ __align__(16) float g_proj[MM * DD];
__device__ __align__(16) float g_x1[MM * DD];
__device__ __align__(16) float g_ff[MM * DFF];
__device__ __align__(16) float g_ff2[MM * DD];

// ---------------- helpers --------------------------------------------------
__device__ __forceinline__ uint32_t f2tf(float f) {
    uint32_t r;
    asm("cvt.rna.tf32.f32 %0, %1;" : "=r"(r) : "f"(f));
    return r;
}

__device__ __forceinline__ uint32_t pkh2(float x, float y) {
    __half2 h = __floats2half2_rn(x, y);
    return *reinterpret_cast<uint32_t*>(&h);
}

__device__ __forceinline__ void mma_tf32(float* c, const uint32_t* a, const uint32_t* b) {
    asm volatile(
        "mma.sync.aligned.m16n8k8.row.col.f32.tf32.tf32.f32 "
        "{%0,%1,%2,%3},{%4,%5,%6,%7},{%8,%9},{%0,%1,%2,%3};\n"
        : "+f"(c[0]), "+f"(c[1]), "+f"(c[2]), "+f"(c[3])
        : "r"(a[0]), "r"(a[1]), "r"(a[2]), "r"(a[3]), "r"(b[0]), "r"(b[1]));
}

__device__ __forceinline__ void mma_f16(float* c, const uint32_t* a, const uint32_t* b) {
    asm volatile(
        "mma.sync.aligned.m16n8k16.row.col.f32.f16.f16.f32 "
        "{%0,%1,%2,%3},{%4,%5,%6,%7},{%8,%9},{%0,%1,%2,%3};\n"
        : "+f"(c[0]), "+f"(c[1]), "+f"(c[2]), "+f"(c[3])
        : "r"(a[0]), "r"(a[1]), "r"(a[2]), "r"(a[3]), "r"(b[0]), "r"(b[1]));
}

__device__ __forceinline__ void ldsm4(uint32_t* r, uint32_t addr) {
    asm volatile("ldmatrix.sync.aligned.m8n8.x4.shared.b16 {%0,%1,%2,%3}, [%4];"
                 : "=r"(r[0]), "=r"(r[1]), "=r"(r[2]), "=r"(r[3]) : "r"(addr));
}
__device__ __forceinline__ void ldsm2(uint32_t* r, uint32_t addr) {
    asm volatile("ldmatrix.sync.aligned.m8n8.x2.shared.b16 {%0,%1}, [%2];"
                 : "=r"(r[0]), "=r"(r[1]) : "r"(addr));
}

// ---------------- FP16 tensor-core GEMM ------------------------------------
// C[M,N] = A[M,K] @ W[N,K]^T + bias (+gelu).  BM in {64,128}, BN=128, BK=32.
// fp16 operands (same 10-bit mantissa as tf32), fp32 accumulate.
// 256 threads = 8 warps; warp tile = (BM/2) x 32 via (BM/32)x4 m16n8k16 tiles.
// blockIdx.z selects among up to 3 (W,bias,C) triples sharing the same A.
template<int GELU, int BM>
__global__ __launch_bounds__(256)
void gemm_fp16(int K, int N, const float* __restrict__ A,
               const float* __restrict__ W0, const float* __restrict__ bia0, float* __restrict__ C0,
               const float* __restrict__ W1, const float* __restrict__ bia1, float* __restrict__ C1,
               const float* __restrict__ W2, const float* __restrict__ bia2, float* __restrict__ C2)
{
    constexpr int MI  = BM / 32;   // m16 tiles per warp
    constexpr int LDH = 40;        // halves per smem row (80B stride: ldmatrix conflict-free)
    __shared__ __half As[2][BM][LDH];
    __shared__ __half Bs[2][128][LDH];

    const int z = blockIdx.z;
    const float* W   = (z == 0) ? W0   : (z == 1) ? W1   : W2;
    const float* bia = (z == 0) ? bia0 : (z == 1) ? bia1 : bia2;
    float*       C   = (z == 0) ? C0   : (z == 1) ? C1   : C2;

    const int tid  = threadIdx.x;
    const int lane = tid & 31;
    const int wid  = tid >> 5;
    const int wm   = (wid >> 2) * (BM / 2);
    const int wn   = (wid & 3) * 32;
    const int l4   = lane >> 2;
    const int lm   = lane & 3;

    const float* Ag = A + (size_t)blockIdx.y * BM * K;
    const float* Wg = W + (size_t)blockIdx.x * 128 * K;

    // staging: 8-float chunks. chunk c -> row c>>2, k-offset (c&3)*8
    const int rA0 = tid >> 2,          kA0 = (tid & 3) * 8;
    const int rB1 = (tid + 256) >> 2;  // second B chunk (and A chunk for BM=128)

    // ldmatrix per-thread source rows (halves offsets within a row handled below)
    const int rA  = (lane & 7) + ((lane >> 3) & 1) * 8;  // 0..15
    const int kA  = (lane >> 4) * 8;                     // 0 or 8
    const int lB  = lane & 15;
    const int rB  = lB & 7;
    const int kB  = (lB >> 3) * 8;

    const uint32_t as_base = (uint32_t)__cvta_generic_to_shared(&As[0][0][0]);
    const uint32_t bs_base = (uint32_t)__cvta_generic_to_shared(&Bs[0][0][0]);
    // per-thread invariant parts (in halves)
    const uint32_t aRowOfs = (uint32_t)((wm + rA) * LDH + kA);
    const uint32_t bRowOfs = (uint32_t)((wn + rB) * LDH + kB);

    float acc[MI][4][4];
    #pragma unroll
    for (int i = 0; i < MI; ++i)
        #pragma unroll
        for (int j = 0; j < 4; ++j)
            #pragma unroll
            for (int r = 0; r < 4; ++r) acc[i][j][r] = 0.f;

    float4 ra0, ra1, ra2, ra3, rb0, rb1, rb2, rb3;

    auto load_tile = [&](int k0) {
        ra0 = *reinterpret_cast<const float4*>(Ag + (size_t)rA0 * K + k0 + kA0);
        ra1 = *reinterpret_cast<const float4*>(Ag + (size_t)rA0 * K + k0 + kA0 + 4);
        if (BM == 128) {
            ra2 = *reinterpret_cast<const float4*>(Ag + (size_t)rB1 * K + k0 + kA0);
            ra3 = *reinterpret_cast<const float4*>(Ag + (size_t)rB1 * K + k0 + kA0 + 4);
        }
        rb0 = *reinterpret_cast<const float4*>(Wg + (size_t)rA0 * K + k0 + kA0);
        rb1 = *reinterpret_cast<const float4*>(Wg + (size_t)rA0 * K + k0 + kA0 + 4);
        rb2 = *reinterpret_cast<const float4*>(Wg + (size_t)rB1 * K + k0 + kA0);
        rb3 = *reinterpret_cast<const float4*>(Wg + (size_t)rB1 * K + k0 + kA0 + 4);
    };
    auto store_tile = [&](int bf) {
        *reinterpret_cast<uint4*>(&As[bf][rA0][kA0]) = make_uint4(
            pkh2(ra0.x, ra0.y), pkh2(ra0.z, ra0.w), pkh2(ra1.x, ra1.y), pkh2(ra1.z, ra1.w));
        if (BM == 128)
            *reinterpret_cast<uint4*>(&As[bf][rB1][kA0]) = make_uint4(
                pkh2(ra2.x, ra2.y), pkh2(ra2.z, ra2.w), pkh2(ra3.x, ra3.y), pkh2(ra3.z, ra3.w));
        *reinterpret_cast<uint4*>(&Bs[bf][rA0][kA0]) = make_uint4(
            pkh2(rb0.x, rb0.y), pkh2(rb0.z, rb0.w), pkh2(rb1.x, rb1.y), pkh2(rb1.z, rb1.w));
        *reinterpret_cast<uint4*>(&Bs[bf][rB1][kA0]) = make_uint4(
            pkh2(rb2.x, rb2.y), pkh2(rb2.z, rb2.w), pkh2(rb3.x, rb3.y), pkh2(rb3.z, rb3.w));
    };
    auto compute = [&](int bf) {
        const uint32_t abuf = as_base + (uint32_t)(bf * BM * LDH) * 2;
        const uint32_t bbuf = bs_base + (uint32_t)(bf * 128 * LDH) * 2;
        #pragma unroll
        for (int ks = 0; ks < 2; ++ks) {           // two k16 steps in BK=32
            uint32_t af[MI][4], bfr[4][2];
            #pragma unroll
            for (int i = 0; i < MI; ++i)
                ldsm4(af[i], abuf + (aRowOfs + (uint32_t)(i * 16 * LDH + ks * 16)) * 2);
            #pragma unroll
            for (int j = 0; j < 4; ++j)
                ldsm2(bfr[j], bbuf + (bRowOfs + (uint32_t)(j * 8 * LDH + ks * 16)) * 2);
            #pragma unroll
            for (int i = 0; i < MI; ++i)
                #pragma unroll
                for (int j = 0; j < 4; ++j)
                    mma_f16(acc[i][j], af[i], bfr[j]);
        }
    };

    load_tile(0);
    store_tile(0);
    __syncthreads();

    int buf = 0;
    for (int k0 = 32; k0 < K; k0 += 32) {
        load_tile(k0);
        compute(buf);
        store_tile(buf ^ 1);
        __syncthreads();
        buf ^= 1;
    }
    compute(buf);

    #pragma unroll
    for (int i = 0; i < MI; ++i) {
        const int row = blockIdx.y * BM + wm + i * 16 + l4;
        #pragma unroll
        for (int j = 0; j < 4; ++j) {
            const int col = blockIdx.x * 128 + wn + j * 8 + lm * 2;
            const float bv0 = bia[col], bv1 = bia[col + 1];
            float v0 = acc[i][j][0] + bv0;
            float v1 = acc[i][j][1] + bv1;
            float v2 = acc[i][j][2] + bv0;
            float v3 = acc[i][j][3] + bv1;
            if (GELU) {
                v0 = 0.5f * v0 * (1.f + erff(v0 * 0.70710678118654752f));
                v1 = 0.5f * v1 * (1.f + erff(v1 * 0.70710678118654752f));
                v2 = 0.5f * v2 * (1.f + erff(v2 * 0.70710678118654752f));
                v3 = 0.5f * v3 * (1.f + erff(v3 * 0.70710678118654752f));
            }
            *reinterpret_cast<float2*>(C + (size_t)row * N + col)       = make_float2(v0, v1);
            *reinterpret_cast<float2*>(C + (size_t)(row + 8) * N + col) = make_float2(v2, v3);
        }
    }
}

// ---------------- Attention: flash-style with tf32 MMA ---------------------
// 64 queries per block, 4 warps (16 q each), 64-key tiles.
// smem (dynamic, 53504 B): Ks[64][68], Vs[64][72], Ps[64][68] (uint32 tf32), msk[64]
#define ATTN_SMEM 53504
__global__ __launch_bounds__(128)
void attn_mma(const float* __restrict__ q,
              const float* __restrict__ k,
              const float* __restrict__ v,
              const float* __restrict__ mask,
              float* __restrict__ out)
{
    extern __shared__ uint32_t smw[];
    uint32_t (*Ks)[68] = (uint32_t(*)[68])smw;                 // 4352 words
    uint32_t (*Vs)[72] = (uint32_t(*)[72])(smw + 4352);        // 4608 words
    uint32_t (*Ps)[68] = (uint32_t(*)[68])(smw + 4352 + 4608); // 4352 words
    float*    msk      = (float*)(smw + 4352 + 4608 + 4352);   // 64 words

    const int b    = blockIdx.z;
    const int h    = blockIdx.y;
    const int q0   = blockIdx.x * 64;
    const int tid  = threadIdx.x;
    const int w    = tid >> 5;
    const int lane = tid & 31;
    const int g    = lane >> 2;   // group row (0..7)
    const int tg   = lane & 3;    // thread-in-group (cols)

    const size_t boff = (size_t)b * SS;
    const int hofs = h * HD;
    const int rlo = q0 + w * 16 + g;
    const int prow = w * 16 + g;

    uint32_t qa[8][4];
    {
        const float* qlo = q + (boff + rlo) * DD + hofs;
        const float* qhi = qlo + 8 * DD;
        #pragma unroll
        for (int ks = 0; ks < 8; ++ks) {
            qa[ks][0] = f2tf(0.125f * qlo[ks * 8 + tg]);
            qa[ks][1] = f2tf(0.125f * qhi[ks * 8 + tg]);
            qa[ks][2] = f2tf(0.125f * qlo[ks * 8 + tg + 4]);
            qa[ks][3] = f2tf(0.125f * qhi[ks * 8 + tg + 4]);
        }
    }

    float o[8][4];
    #pragma unroll
    for (int j = 0; j < 8; ++j)
        #pragma unroll
        for (int r = 0; r < 4; ++r) o[j][r] = 0.f;
    float mx_lo = -1e30f, mx_hi = -1e30f, l_lo = 0.f, l_hi = 0.f;

    for (int kt = 0; kt < SS; kt += 64) {
        __syncthreads();
        #pragma unroll
        for (int it = 0; it < 8; ++it) {
            const int idx = it * 128 + tid;
            const int r = idx >> 4, c = (idx & 15) << 2;
            const float4 kv = *reinterpret_cast<const float4*>(
                k + (boff + kt + r) * DD + hofs + c);
            const float4 vv = *reinterpret_cast<const float4*>(
                v + (boff + kt + r) * DD + hofs + c);
            *reinterpret_cast<uint4*>(&Ks[r][c]) =
                make_uint4(f2tf(kv.x), f2tf(kv.y), f2tf(kv.z), f2tf(kv.w));
            *reinterpret_cast<uint4*>(&Vs[r][c]) =
                make_uint4(f2tf(vv.x), f2tf(vv.y), f2tf(vv.z), f2tf(vv.w));
        }
        if (tid < 64) msk[tid] = -10000.f * (1.f - mask[boff + kt + tid]);
        __syncthreads();

        float sc[8][4];
        #pragma unroll
        for (int j = 0; j < 8; ++j) {
            sc[j][0] = sc[j][1] = sc[j][2] = sc[j][3] = 0.f;
            #pragma unroll
            for (int ks = 0; ks < 8; ++ks) {
                uint32_t bb[2];
                bb[0] = Ks[j * 8 + g][ks * 8 + tg];
                bb[1] = Ks[j * 8 + g][ks * 8 + tg + 4];
                mma_tf32(sc[j], qa[ks], bb);
            }
        }

        float nm_lo = mx_lo, nm_hi = mx_hi;
        #pragma unroll
        for (int j = 0; j < 8; ++j) {
            const float m0 = msk[j * 8 + 2 * tg], m1 = msk[j * 8 + 2 * tg + 1];
            sc[j][0] += m0; sc[j][1] += m1; sc[j][2] += m0; sc[j][3] += m1;
            nm_lo = fmaxf(nm_lo, fmaxf(sc[j][0], sc[j][1]));
            nm_hi = fmaxf(nm_hi, fmaxf(sc[j][2], sc[j][3]));
        }
        nm_lo = fmaxf(nm_lo, __shfl_xor_sync(0xFFFFFFFFu, nm_lo, 1));
        nm_lo = fmaxf(nm_lo, __shfl_xor_sync(0xFFFFFFFFu, nm_lo, 2));
        nm_hi = fmaxf(nm_hi, __shfl_xor_sync(0xFFFFFFFFu, nm_hi, 1));
        nm_hi = fmaxf(nm_hi, __shfl_xor_sync(0xFFFFFFFFu, nm_hi, 2));
        const float cor_lo = __expf(mx_lo - nm_lo);
        const float cor_hi = __expf(mx_hi - nm_hi);
        mx_lo = nm_lo; mx_hi = nm_hi;

        float sl_lo = 0.f, sl_hi = 0.f;
        #pragma unroll
        for (int j = 0; j < 8; ++j) {
            const float p0 = __expf(sc[j][0] - mx_lo);
            const float p1 = __expf(sc[j][1] - mx_lo);
            const float p2 = __expf(sc[j][2] - mx_hi);
            const float p3 = __expf(sc[j][3] - mx_hi);
            sl_lo += p0 + p1; sl_hi += p2 + p3;
            *reinterpret_cast<uint2*>(&Ps[prow][j * 8 + 2 * tg]) =
                make_uint2(f2tf(p0), f2tf(p1));
            *reinterpret_cast<uint2*>(&Ps[prow + 8][j * 8 + 2 * tg]) =
                make_uint2(f2tf(p2), f2tf(p3));
            o[j][0] *= cor_lo; o[j][1] *= cor_lo;
            o[j][2] *= cor_hi; o[j][3] *= cor_hi;
        }
        sl_lo += __shfl_xor_sync(0xFFFFFFFFu, sl_lo, 1);
        sl_lo += __shfl_xor_sync(0xFFFFFFFFu, sl_lo, 2);
        sl_hi += __shfl_xor_sync(0xFFFFFFFFu, sl_hi, 1);
        sl_hi += __shfl_xor_sync(0xFFFFFFFFu, sl_hi, 2);
        l_lo = l_lo * cor_lo + sl_lo;
        l_hi = l_hi * cor_hi + sl_hi;
        __syncwarp();

        #pragma unroll
        for (int ks = 0; ks < 8; ++ks) {
            uint32_t a[4];
            a[0] = Ps[w * 16 + g][ks * 8 + tg];
            a[1] = Ps[w * 16 + g + 8][ks * 8 + tg];
            a[2] = Ps[w * 16 + g][ks * 8 + tg + 4];
            a[3] = Ps[w * 16 + g + 8][ks * 8 + tg + 4];
            #pragma unroll
            for (int j = 0; j < 8; ++j) {
                uint32_t bb[2];
                bb[0] = Vs[ks * 8 + tg][j * 8 + g];
                bb[1] = Vs[ks * 8 + tg + 4][j * 8 + g];
                mma_tf32(o[j], a, bb);
            }
        }
        __syncwarp();
    }

    const float inv_lo = 1.f / l_lo;
    const float inv_hi = 1.f / l_hi;
    float* olo = out + (boff + rlo) * DD + hofs;
    float* ohi = olo + 8 * DD;
    #pragma unroll
    for (int j = 0; j < 8; ++j) {
        *reinterpret_cast<float2*>(olo + j * 8 + 2 * tg) =
            make_float2(o[j][0] * inv_lo, o[j][1] * inv_lo);
        *reinterpret_cast<float2*>(ohi + j * 8 + 2 * tg) =
            make_float2(o[j][2] * inv_hi, o[j][3] * inv_hi);
    }
}

// ---------------- Fused residual-add + LayerNorm ---------------------------
__global__ __launch_bounds__(256)
void ln_kernel(const float* __restrict__ a, const float* __restrict__ r,
               const float* __restrict__ gamma, const float* __restrict__ beta,
               float* __restrict__ out)
{
    const size_t base = (size_t)blockIdx.x * DD;
    const int t = threadIdx.x;

    const float v0 = a[base + t]       + r[base + t];
    const float v1 = a[base + t + 256] + r[base + t + 256];
    const float v2 = a[base + t + 512] + r[base + t + 512];

    float s  = v0 + v1 + v2;
    float ss = v0 * v0 + v1 * v1 + v2 * v2;
    #pragma unroll
    for (int o = 16; o > 0; o >>= 1) {
        s  += __shfl_xor_sync(0xFFFFFFFFu, s,  o);
        ss += __shfl_xor_sync(0xFFFFFFFFu, ss, o);
    }
    __shared__ float rs[8], rss[8], stats[2];
    const int wid = t >> 5, lid = t & 31;
    if (lid == 0) { rs[wid] = s; rss[wid] = ss; }
    __syncthreads();
    if (t == 0) {
        float S = 0.f, SSq = 0.f;
        #pragma unroll
        for (int i = 0; i < 8; ++i) { S += rs[i]; SSq += rss[i]; }
        const float mu  = S * (1.f / DD);
        const float var = SSq * (1.f / DD) - mu * mu;
        stats[0] = mu;
        stats[1] = rsqrtf(var + 1e-12f);
    }
    __syncthreads();
    const float mu = stats[0], rstd = stats[1];

    out[base + t]       = gamma[t]       * (v0 - mu) * rstd + beta[t];
    out[base + t + 256] = gamma[t + 256] * (v1 - mu) * rstd + beta[t + 256];
    out[base + t + 512] = gamma[t + 512] * (v2 - mu) * rstd + beta[t + 512];
}

// ---------------- launcher -------------------------------------------------
extern "C" void kernel_launch(void* const* d_in, const int* in_sizes, int n_in,
                              void* d_out, int out_size)
{
    const float* x    = (const float*)d_in[0];
    const float* mask = (const float*)d_in[1];
    const float* Wq   = (const float*)d_in[2];
    const float* bq   = (const float*)d_in[3];
    const float* Wk   = (const float*)d_in[4];
    const float* bk   = (const float*)d_in[5];
    const float* Wv   = (const float*)d_in[6];
    const float* bv   = (const float*)d_in[7];
    const float* Wp   = (const float*)d_in[8];
    const float* bp   = (const float*)d_in[9];
    const float* g1   = (const float*)d_in[10];
    const float* be1  = (const float*)d_in[11];
    const float* W1   = (const float*)d_in[12];
    const float* bf1  = (const float*)d_in[13];
    const float* W2   = (const float*)d_in[14];
    const float* bf2  = (const float*)d_in[15];
    const float* g2   = (const float*)d_in[16];
    const float* be2  = (const float*)d_in[17];
    float* outp = (float*)d_out;

    float *pq, *pk, *pv, *pattn, *pproj, *px1, *pff, *pff2;
    cudaGetSymbolAddress((void**)&pq,    g_q);
    cudaGetSymbolAddress((void**)&pk,    g_k);
    cudaGetSymbolAddress((void**)&pv,    g_v);
    cudaGetSymbolAddress((void**)&pattn, g_attn);
    cudaGetSymbolAddress((void**)&pproj, g_proj);
    cudaGetSymbolAddress((void**)&px1,   g_x1);
    cudaGetSymbolAddress((void**)&pff,   g_ff);
    cudaGetSymbolAddress((void**)&pff2,  g_ff2);

    cudaFuncSetAttribute(attn_mma, cudaFuncAttributeMaxDynamicSharedMemorySize, ATTN_SMEM);

    const dim3 blk(256);

    // QKV projections: one launch, z selects W/bias/out (576 blocks)
    gemm_fp16<0, 128><<<dim3(DD / 128, MM / 128, 3), blk>>>(
        DD, DD, x, Wq, bq, pq, Wk, bk, pk, Wv, bv, pv);

    // Attention (tensor-core flash)
    attn_mma<<<dim3(SS / 64, HH, BB), 128, ATTN_SMEM>>>(pq, pk, pv, mask, pattn);

    // Output projection (BM=64 -> 384 blocks) + residual + LN1
    gemm_fp16<0, 64><<<dim3(DD / 128, MM / 64, 1), blk>>>(
        DD, DD, pattn, Wp, bp, pproj, Wp, bp, pproj, Wp, bp, pproj);
    ln_kernel<<<MM, 256>>>(x, pproj, g1, be1, px1);

    // FFN
    gemm_fp16<1, 128><<<dim3(DFF / 128, MM / 128, 1), blk>>>(
        DD, DFF, px1, W1, bf1, pff, W1, bf1, pff, W1, bf1, pff);
    gemm_fp16<0, 64><<<dim3(DD / 128, MM / 64, 1), blk>>>(
        DFF, DD, pff, W2, bf2, pff2, W2, bf2, pff2, W2, bf2, pff2);

    // Residual + LN2 -> output
    ln_kernel<<<MM, 256>>>(px1, pff2, g2, be2, outp);
}

// round 7
// speedup vs baseline: 6.0279x; 1.1461x over previous
#include <cuda_runtime.h>
#include <cuda_bf16.h>
#include <cuda_fp16.h>
#include <math.h>
#include <stdint.h>

// Problem dims (fixed by dataset)
#define BB 2
#define SS 2048
#define DD 768
#define HH 12
#define HD 64
#define DFF 3072
#define MM (BB * SS)   // 4096 tokens

// ---------------- scratch (no allocations allowed) ----------------
__device__ __align__(16) float g_q[MM * DD];
__device__ __align__(16) float g_k[MM * DD];
__device__ __align__(16) float g_v[MM * DD];
__device__ __align__(16) float g_attn[MM * DD];
__device__ __align__(16) float g_proj[MM * DD];
__device__ __align__(16) float g_x1[MM * DD];
__device__ __align__(16) float g_ff[MM * DFF];
__device__ __align__(16) float g_ff2[MM * DD];

// ---------------- helpers --------------------------------------------------
__device__ __forceinline__ uint32_t pkh2(float x, float y) {
    __half2 h = __floats2half2_rn(x, y);
    return *reinterpret_cast<uint32_t*>(&h);
}

__device__ __forceinline__ void mma_f16(float* c, const uint32_t* a, const uint32_t* b) {
    asm volatile(
        "mma.sync.aligned.m16n8k16.row.col.f32.f16.f16.f32 "
        "{%0,%1,%2,%3},{%4,%5,%6,%7},{%8,%9},{%0,%1,%2,%3};\n"
        : "+f"(c[0]), "+f"(c[1]), "+f"(c[2]), "+f"(c[3])
        : "r"(a[0]), "r"(a[1]), "r"(a[2]), "r"(a[3]), "r"(b[0]), "r"(b[1]));
}

__device__ __forceinline__ void ldsm4(uint32_t* r, uint32_t addr) {
    asm volatile("ldmatrix.sync.aligned.m8n8.x4.shared.b16 {%0,%1,%2,%3}, [%4];"
                 : "=r"(r[0]), "=r"(r[1]), "=r"(r[2]), "=r"(r[3]) : "r"(addr));
}
__device__ __forceinline__ void ldsm2(uint32_t* r, uint32_t addr) {
    asm volatile("ldmatrix.sync.aligned.m8n8.x2.shared.b16 {%0,%1}, [%2];"
                 : "=r"(r[0]), "=r"(r[1]) : "r"(addr));
}
__device__ __forceinline__ void ldsm2t(uint32_t* r, uint32_t addr) {
    asm volatile("ldmatrix.sync.aligned.m8n8.x2.trans.shared.b16 {%0,%1}, [%2];"
                 : "=r"(r[0]), "=r"(r[1]) : "r"(addr));
}

// ---------------- FP16 tensor-core GEMM ------------------------------------
// C[M,N] = A[M,K] @ W[N,K]^T + bias (+gelu).  BM in {64,128}, BN=128, BK=32.
// fp16 operands (same 10-bit mantissa as tf32), fp32 accumulate.
// 256 threads = 8 warps; warp tile = (BM/2) x 32 via (BM/32)x4 m16n8k16 tiles.
// blockIdx.z selects among up to 3 (W,bias,C) triples sharing the same A.
template<int GELU, int BM>
__global__ __launch_bounds__(256)
void gemm_fp16(int K, int N, const float* __restrict__ A,
               const float* __restrict__ W0, const float* __restrict__ bia0, float* __restrict__ C0,
               const float* __restrict__ W1, const float* __restrict__ bia1, float* __restrict__ C1,
               const float* __restrict__ W2, const float* __restrict__ bia2, float* __restrict__ C2)
{
    constexpr int MI  = BM / 32;   // m16 tiles per warp
    constexpr int LDH = 40;        // halves per smem row (80B stride: ldmatrix conflict-free)
    __shared__ __half As[2][BM][LDH];
    __shared__ __half Bs[2][128][LDH];

    const int z = blockIdx.z;
    const float* W   = (z == 0) ? W0   : (z == 1) ? W1   : W2;
    const float* bia = (z == 0) ? bia0 : (z == 1) ? bia1 : bia2;
    float*       C   = (z == 0) ? C0   : (z == 1) ? C1   : C2;

    const int tid  = threadIdx.x;
    const int lane = tid & 31;
    const int wid  = tid >> 5;
    const int wm   = (wid >> 2) * (BM / 2);
    const int wn   = (wid & 3) * 32;
    const int l4   = lane >> 2;
    const int lm   = lane & 3;

    const float* Ag = A + (size_t)blockIdx.y * BM * K;
    const float* Wg = W + (size_t)blockIdx.x * 128 * K;

    const int rA0 = tid >> 2,          kA0 = (tid & 3) * 8;
    const int rB1 = (tid + 256) >> 2;

    const int rA  = (lane & 7) + ((lane >> 3) & 1) * 8;
    const int kA  = (lane >> 4) * 8;
    const int lB  = lane & 15;
    const int rB  = lB & 7;
    const int kB  = (lB >> 3) * 8;

    const uint32_t as_base = (uint32_t)__cvta_generic_to_shared(&As[0][0][0]);
    const uint32_t bs_base = (uint32_t)__cvta_generic_to_shared(&Bs[0][0][0]);
    const uint32_t aRowOfs = (uint32_t)((wm + rA) * LDH + kA);
    const uint32_t bRowOfs = (uint32_t)((wn + rB) * LDH + kB);

    float acc[MI][4][4];
    #pragma unroll
    for (int i = 0; i < MI; ++i)
        #pragma unroll
        for (int j = 0; j < 4; ++j)
            #pragma unroll
            for (int r = 0; r < 4; ++r) acc[i][j][r] = 0.f;

    float4 ra0, ra1, ra2, ra3, rb0, rb1, rb2, rb3;

    auto load_tile = [&](int k0) {
        ra0 = *reinterpret_cast<const float4*>(Ag + (size_t)rA0 * K + k0 + kA0);
        ra1 = *reinterpret_cast<const float4*>(Ag + (size_t)rA0 * K + k0 + kA0 + 4);
        if (BM == 128) {
            ra2 = *reinterpret_cast<const float4*>(Ag + (size_t)rB1 * K + k0 + kA0);
            ra3 = *reinterpret_cast<const float4*>(Ag + (size_t)rB1 * K + k0 + kA0 + 4);
        }
        rb0 = *reinterpret_cast<const float4*>(Wg + (size_t)rA0 * K + k0 + kA0);
        rb1 = *reinterpret_cast<const float4*>(Wg + (size_t)rA0 * K + k0 + kA0 + 4);
        rb2 = *reinterpret_cast<const float4*>(Wg + (size_t)rB1 * K + k0 + kA0);
        rb3 = *reinterpret_cast<const float4*>(Wg + (size_t)rB1 * K + k0 + kA0 + 4);
    };
    auto store_tile = [&](int bf) {
        *reinterpret_cast<uint4*>(&As[bf][rA0][kA0]) = make_uint4(
            pkh2(ra0.x, ra0.y), pkh2(ra0.z, ra0.w), pkh2(ra1.x, ra1.y), pkh2(ra1.z, ra1.w));
        if (BM == 128)
            *reinterpret_cast<uint4*>(&As[bf][rB1][kA0]) = make_uint4(
                pkh2(ra2.x, ra2.y), pkh2(ra2.z, ra2.w), pkh2(ra3.x, ra3.y), pkh2(ra3.z, ra3.w));
        *reinterpret_cast<uint4*>(&Bs[bf][rA0][kA0]) = make_uint4(
            pkh2(rb0.x, rb0.y), pkh2(rb0.z, rb0.w), pkh2(rb1.x, rb1.y), pkh2(rb1.z, rb1.w));
        *reinterpret_cast<uint4*>(&Bs[bf][rB1][kA0]) = make_uint4(
            pkh2(rb2.x, rb2.y), pkh2(rb2.z, rb2.w), pkh2(rb3.x, rb3.y), pkh2(rb3.z, rb3.w));
    };
    auto compute = [&](int bf) {
        const uint32_t abuf = as_base + (uint32_t)(bf * BM * LDH) * 2;
        const uint32_t bbuf = bs_base + (uint32_t)(bf * 128 * LDH) * 2;
        #pragma unroll
        for (int ks = 0; ks < 2; ++ks) {
            uint32_t af[MI][4], bfr[4][2];
            #pragma unroll
            for (int i = 0; i < MI; ++i)
                ldsm4(af[i], abuf + (aRowOfs + (uint32_t)(i * 16 * LDH + ks * 16)) * 2);
            #pragma unroll
            for (int j = 0; j < 4; ++j)
                ldsm2(bfr[j], bbuf + (bRowOfs + (uint32_t)(j * 8 * LDH + ks * 16)) * 2);
            #pragma unroll
            for (int i = 0; i < MI; ++i)
                #pragma unroll
                for (int j = 0; j < 4; ++j)
                    mma_f16(acc[i][j], af[i], bfr[j]);
        }
    };

    load_tile(0);
    store_tile(0);
    __syncthreads();

    int buf = 0;
    for (int k0 = 32; k0 < K; k0 += 32) {
        load_tile(k0);
        compute(buf);
        store_tile(buf ^ 1);
        __syncthreads();
        buf ^= 1;
    }
    compute(buf);

    #pragma unroll
    for (int i = 0; i < MI; ++i) {
        const int row = blockIdx.y * BM + wm + i * 16 + l4;
        #pragma unroll
        for (int j = 0; j < 4; ++j) {
            const int col = blockIdx.x * 128 + wn + j * 8 + lm * 2;
            const float bv0 = bia[col], bv1 = bia[col + 1];
            float v0 = acc[i][j][0] + bv0;
            float v1 = acc[i][j][1] + bv1;
            float v2 = acc[i][j][2] + bv0;
            float v3 = acc[i][j][3] + bv1;
            if (GELU) {
                v0 = 0.5f * v0 * (1.f + erff(v0 * 0.70710678118654752f));
                v1 = 0.5f * v1 * (1.f + erff(v1 * 0.70710678118654752f));
                v2 = 0.5f * v2 * (1.f + erff(v2 * 0.70710678118654752f));
                v3 = 0.5f * v3 * (1.f + erff(v3 * 0.70710678118654752f));
            }
            *reinterpret_cast<float2*>(C + (size_t)row * N + col)       = make_float2(v0, v1);
            *reinterpret_cast<float2*>(C + (size_t)(row + 8) * N + col) = make_float2(v2, v3);
        }
    }
}

// ---------------- Attention: FA2-style fp16 MMA ----------------------------
// 64 queries/block, 4 warps (16 q each), 64-key tiles. P stays in registers:
// score-fragment pairs repacked as half2 form the A fragment of the PV MMA.
#define AT_LDH 72   // halves per smem row (144B): ldmatrix phases conflict-free
__global__ __launch_bounds__(128)
void attn_f16(const float* __restrict__ q,
              const float* __restrict__ k,
              const float* __restrict__ v,
              const float* __restrict__ mask,
              float* __restrict__ out)
{
    __shared__ __half Ks[64][AT_LDH];
    __shared__ __half Vs[64][AT_LDH];
    __shared__ float  msk[64];

    const int b    = blockIdx.z;
    const int h    = blockIdx.y;
    const int q0   = blockIdx.x * 64;
    const int tid  = threadIdx.x;
    const int w    = tid >> 5;
    const int lane = tid & 31;
    const int g    = lane >> 2;   // fragment row (0..7)
    const int tg   = lane & 3;    // fragment col pair
    const int lB   = lane & 15;
    const int rBk  = lB & 7;
    const int kBk  = (lB >> 3) * 8;

    const size_t boff = (size_t)b * SS;
    const int hofs = h * HD;
    const int rlo  = q0 + w * 16 + g;

    const uint32_t ks_base = (uint32_t)__cvta_generic_to_shared(&Ks[0][0]);
    const uint32_t vs_base = (uint32_t)__cvta_generic_to_shared(&Vs[0][0]);

    // Q fragments (pre-scaled by 1/8), registers for whole kernel
    uint32_t qa[4][4];
    {
        const float* qlo = q + (boff + rlo) * DD + hofs;
        const float* qhi = qlo + 8 * DD;
        #pragma unroll
        for (int ks = 0; ks < 4; ++ks) {
            const int c0 = ks * 16 + 2 * tg;
            qa[ks][0] = pkh2(0.125f * qlo[c0],     0.125f * qlo[c0 + 1]);
            qa[ks][1] = pkh2(0.125f * qhi[c0],     0.125f * qhi[c0 + 1]);
            qa[ks][2] = pkh2(0.125f * qlo[c0 + 8], 0.125f * qlo[c0 + 9]);
            qa[ks][3] = pkh2(0.125f * qhi[c0 + 8], 0.125f * qhi[c0 + 9]);
        }
    }

    float o[8][4];
    #pragma unroll
    for (int j = 0; j < 8; ++j)
        #pragma unroll
        for (int r = 0; r < 4; ++r) o[j][r] = 0.f;
    float mx_lo = -1e30f, mx_hi = -1e30f, l_lo = 0.f, l_hi = 0.f;

    for (int kt = 0; kt < SS; kt += 64) {
        __syncthreads();
        // stage K,V tiles (64x64 fp32 -> fp16), 4 chunks of 8 floats per thread
        #pragma unroll
        for (int it = 0; it < 4; ++it) {
            const int idx = it * 128 + tid;
            const int r = idx >> 3, c = (idx & 7) * 8;
            const float* kp = k + (boff + kt + r) * DD + hofs + c;
            const float* vp = v + (boff + kt + r) * DD + hofs + c;
            const float4 k0 = *reinterpret_cast<const float4*>(kp);
            const float4 k1 = *reinterpret_cast<const float4*>(kp + 4);
            const float4 v0 = *reinterpret_cast<const float4*>(vp);
            const float4 v1 = *reinterpret_cast<const float4*>(vp + 4);
            *reinterpret_cast<uint4*>(&Ks[r][c]) = make_uint4(
                pkh2(k0.x, k0.y), pkh2(k0.z, k0.w), pkh2(k1.x, k1.y), pkh2(k1.z, k1.w));
            *reinterpret_cast<uint4*>(&Vs[r][c]) = make_uint4(
                pkh2(v0.x, v0.y), pkh2(v0.z, v0.w), pkh2(v1.x, v1.y), pkh2(v1.z, v1.w));
        }
        if (tid < 64) msk[tid] = -10000.f * (1.f - mask[boff + kt + tid]);
        __syncthreads();

        // ---- scores S[16q x 64k] per warp: 8 n8 tiles x 4 k16 steps ----
        float sc[8][4];
        #pragma unroll
        for (int j = 0; j < 8; ++j) {
            sc[j][0] = sc[j][1] = sc[j][2] = sc[j][3] = 0.f;
            #pragma unroll
            for (int ks = 0; ks < 4; ++ks) {
                uint32_t bb[2];
                ldsm2(bb, ks_base + (uint32_t)((j * 8 + rBk) * AT_LDH + kBk + ks * 16) * 2);
                mma_f16(sc[j], qa[ks], bb);
            }
        }

        // ---- online softmax ----
        float nm_lo = mx_lo, nm_hi = mx_hi;
        #pragma unroll
        for (int j = 0; j < 8; ++j) {
            const float m0 = msk[j * 8 + 2 * tg], m1 = msk[j * 8 + 2 * tg + 1];
            sc[j][0] += m0; sc[j][1] += m1; sc[j][2] += m0; sc[j][3] += m1;
            nm_lo = fmaxf(nm_lo, fmaxf(sc[j][0], sc[j][1]));
            nm_hi = fmaxf(nm_hi, fmaxf(sc[j][2], sc[j][3]));
        }
        nm_lo = fmaxf(nm_lo, __shfl_xor_sync(0xFFFFFFFFu, nm_lo, 1));
        nm_lo = fmaxf(nm_lo, __shfl_xor_sync(0xFFFFFFFFu, nm_lo, 2));
        nm_hi = fmaxf(nm_hi, __shfl_xor_sync(0xFFFFFFFFu, nm_hi, 1));
        nm_hi = fmaxf(nm_hi, __shfl_xor_sync(0xFFFFFFFFu, nm_hi, 2));
        const float cor_lo = __expf(mx_lo - nm_lo);
        const float cor_hi = __expf(mx_hi - nm_hi);
        mx_lo = nm_lo; mx_hi = nm_hi;

        // exp -> P fragments (registers only)
        uint32_t pa[4][4];
        float sl_lo = 0.f, sl_hi = 0.f;
        #pragma unroll
        for (int j = 0; j < 8; ++j) {
            const float p0 = __expf(sc[j][0] - mx_lo);
            const float p1 = __expf(sc[j][1] - mx_lo);
            const float p2 = __expf(sc[j][2] - mx_hi);
            const float p3 = __expf(sc[j][3] - mx_hi);
            sl_lo += p0 + p1; sl_hi += p2 + p3;
            const int ks = j >> 1;
            if ((j & 1) == 0) {
                pa[ks][0] = pkh2(p0, p1);
                pa[ks][1] = pkh2(p2, p3);
            } else {
                pa[ks][2] = pkh2(p0, p1);
                pa[ks][3] = pkh2(p2, p3);
            }
        }
        sl_lo += __shfl_xor_sync(0xFFFFFFFFu, sl_lo, 1);
        sl_lo += __shfl_xor_sync(0xFFFFFFFFu, sl_lo, 2);
        sl_hi += __shfl_xor_sync(0xFFFFFFFFu, sl_hi, 1);
        sl_hi += __shfl_xor_sync(0xFFFFFFFFu, sl_hi, 2);
        l_lo = l_lo * cor_lo + sl_lo;
        l_hi = l_hi * cor_hi + sl_hi;
        #pragma unroll
        for (int j = 0; j < 8; ++j) {
            o[j][0] *= cor_lo; o[j][1] *= cor_lo;
            o[j][2] *= cor_hi; o[j][3] *= cor_hi;
        }

        // ---- PV: O[16 x 64] += P[16 x 64] * V[64 x 64] (ldmatrix.trans B) --
        #pragma unroll
        for (int ks = 0; ks < 4; ++ks) {
            #pragma unroll
            for (int j = 0; j < 8; ++j) {
                uint32_t bv[2];
                ldsm2t(bv, vs_base + (uint32_t)((ks * 16 + lB) * AT_LDH + j * 8) * 2);
                mma_f16(o[j], pa[ks], bv);
            }
        }
    }

    const float inv_lo = 1.f / l_lo;
    const float inv_hi = 1.f / l_hi;
    float* olo = out + (boff + rlo) * DD + hofs;
    float* ohi = olo + 8 * DD;
    #pragma unroll
    for (int j = 0; j < 8; ++j) {
        *reinterpret_cast<float2*>(olo + j * 8 + 2 * tg) =
            make_float2(o[j][0] * inv_lo, o[j][1] * inv_lo);
        *reinterpret_cast<float2*>(ohi + j * 8 + 2 * tg) =
            make_float2(o[j][2] * inv_hi, o[j][3] * inv_hi);
    }
}

// ---------------- Fused residual-add + LayerNorm ---------------------------
__global__ __launch_bounds__(256)
void ln_kernel(const float* __restrict__ a, const float* __restrict__ r,
               const float* __restrict__ gamma, const float* __restrict__ beta,
               float* __restrict__ out)
{
    const size_t base = (size_t)blockIdx.x * DD;
    const int t = threadIdx.x;

    const float v0 = a[base + t]       + r[base + t];
    const float v1 = a[base + t + 256] + r[base + t + 256];
    const float v2 = a[base + t + 512] + r[base + t + 512];

    float s  = v0 + v1 + v2;
    float ss = v0 * v0 + v1 * v1 + v2 * v2;
    #pragma unroll
    for (int o = 16; o > 0; o >>= 1) {
        s  += __shfl_xor_sync(0xFFFFFFFFu, s,  o);
        ss += __shfl_xor_sync(0xFFFFFFFFu, ss, o);
    }
    __shared__ float rs[8], rss[8], stats[2];
    const int wid = t >> 5, lid = t & 31;
    if (lid == 0) { rs[wid] = s; rss[wid] = ss; }
    __syncthreads();
    if (t == 0) {
        float S = 0.f, SSq = 0.f;
        #pragma unroll
        for (int i = 0; i < 8; ++i) { S += rs[i]; SSq += rss[i]; }
        const float mu  = S * (1.f / DD);
        const float var = SSq * (1.f / DD) - mu * mu;
        stats[0] = mu;
        stats[1] = rsqrtf(var + 1e-12f);
    }
    __syncthreads();
    const float mu = stats[0], rstd = stats[1];

    out[base + t]       = gamma[t]       * (v0 - mu) * rstd + beta[t];
    out[base + t + 256] = gamma[t + 256] * (v1 - mu) * rstd + beta[t + 256];
    out[base + t + 512] = gamma[t + 512] * (v2 - mu) * rstd + beta[t + 512];
}

// ---------------- launcher -------------------------------------------------
extern "C" void kernel_launch(void* const* d_in, const int* in_sizes, int n_in,
                              void* d_out, int out_size)
{
    const float* x    = (const float*)d_in[0];
    const float* mask = (const float*)d_in[1];
    const float* Wq   = (const float*)d_in[2];
    const float* bq   = (const float*)d_in[3];
    const float* Wk   = (const float*)d_in[4];
    const float* bk   = (const float*)d_in[5];
    const float* Wv   = (const float*)d_in[6];
    const float* bv   = (const float*)d_in[7];
    const float* Wp   = (const float*)d_in[8];
    const float* bp   = (const float*)d_in[9];
    const float* g1   = (const float*)d_in[10];
    const float* be1  = (const float*)d_in[11];
    const float* W1   = (const float*)d_in[12];
    const float* bf1  = (const float*)d_in[13];
    const float* W2   = (const float*)d_in[14];
    const float* bf2  = (const float*)d_in[15];
    const float* g2   = (const float*)d_in[16];
    const float* be2  = (const float*)d_in[17];
    float* outp = (float*)d_out;

    float *pq, *pk, *pv, *pattn, *pproj, *px1, *pff, *pff2;
    cudaGetSymbolAddress((void**)&pq,    g_q);
    cudaGetSymbolAddress((void**)&pk,    g_k);
    cudaGetSymbolAddress((void**)&pv,    g_v);
    cudaGetSymbolAddress((void**)&pattn, g_attn);
    cudaGetSymbolAddress((void**)&pproj, g_proj);
    cudaGetSymbolAddress((void**)&px1,   g_x1);
    cudaGetSymbolAddress((void**)&pff,   g_ff);
    cudaGetSymbolAddress((void**)&pff2,  g_ff2);

    const dim3 blk(256);

    // QKV projections: one launch, z selects W/bias/out (576 blocks)
    gemm_fp16<0, 128><<<dim3(DD / 128, MM / 128, 3), blk>>>(
        DD, DD, x, Wq, bq, pq, Wk, bk, pk, Wv, bv, pv);

    // Attention (fp16 tensor-core flash, P in registers)
    attn_f16<<<dim3(SS / 64, HH, BB), 128>>>(pq, pk, pv, mask, pattn);

    // Output projection (BM=64 -> 384 blocks) + residual + LN1
    gemm_fp16<0, 64><<<dim3(DD / 128, MM / 64, 1), blk>>>(
        DD, DD, pattn, Wp, bp, pproj, Wp, bp, pproj, Wp, bp, pproj);
    ln_kernel<<<MM, 256>>>(x, pproj, g1, be1, px1);

    // FFN
    gemm_fp16<1, 128><<<dim3(DFF / 128, MM / 128, 1), blk>>>(
        DD, DFF, px1, W1, bf1, pff, W1, bf1, pff, W1, bf1, pff);
    gemm_fp16<0, 64><<<dim3(DD / 128, MM / 64, 1), blk>>>(
        DFF, DD, pff, W2, bf2, pff2, W2, bf2, pff2, W2, bf2, pff2);

    // Residual + LN2 -> output
    ln_kernel<<<MM, 256>>>(px1, pff2, g2, be2, outp);
}

// round 8
// speedup vs baseline: 7.6977x; 1.2770x over previous
#include <cuda_runtime.h>
#include <cuda_bf16.h>
#include <cuda_fp16.h>
#include <math.h>
#include <stdint.h>

// Problem dims (fixed by dataset)
#define BB 2
#define SS 2048
#define DD 768
#define HH 12
#define HD 64
#define DFF 3072
#define MM (BB * SS)   // 4096 tokens

// ---------------- scratch (no allocations allowed) ----------------
__device__ __align__(16) __half h_x [MM * DD];
__device__ __align__(16) __half h_wq[DD * DD];
__device__ __align__(16) __half h_wk[DD * DD];
__device__ __align__(16) __half h_wv[DD * DD];
__device__ __align__(16) __half h_wp[DD * DD];
__device__ __align__(16) __half h_w1[DFF * DD];
__device__ __align__(16) __half h_w2[DD * DFF];
__device__ __align__(16) __half h_q [MM * DD];
__device__ __align__(16) __half h_k [MM * DD];
__device__ __align__(16) __half h_v [MM * DD];
__device__ __align__(16) __half h_at[MM * DD];
__device__ __align__(16) __half h_x1[MM * DD];
__device__ __align__(16) __half h_ff[MM * DFF];
__device__ __align__(16) float  g_proj[MM * DD];
__device__ __align__(16) float  g_x1f [MM * DD];
__device__ __align__(16) float  g_ff2 [MM * DD];

// ---------------- helpers --------------------------------------------------
__device__ __forceinline__ uint32_t pkh2(float x, float y) {
    __half2 h = __floats2half2_rn(x, y);
    return *reinterpret_cast<uint32_t*>(&h);
}

__device__ __forceinline__ void mma_f16(float* c, const uint32_t* a, const uint32_t* b) {
    asm volatile(
        "mma.sync.aligned.m16n8k16.row.col.f32.f16.f16.f32 "
        "{%0,%1,%2,%3},{%4,%5,%6,%7},{%8,%9},{%0,%1,%2,%3};\n"
        : "+f"(c[0]), "+f"(c[1]), "+f"(c[2]), "+f"(c[3])
        : "r"(a[0]), "r"(a[1]), "r"(a[2]), "r"(a[3]), "r"(b[0]), "r"(b[1]));
}

__device__ __forceinline__ void ldsm4(uint32_t* r, uint32_t addr) {
    asm volatile("ldmatrix.sync.aligned.m8n8.x4.shared.b16 {%0,%1,%2,%3}, [%4];"
                 : "=r"(r[0]), "=r"(r[1]), "=r"(r[2]), "=r"(r[3]) : "r"(addr));
}
__device__ __forceinline__ void ldsm2(uint32_t* r, uint32_t addr) {
    asm volatile("ldmatrix.sync.aligned.m8n8.x2.shared.b16 {%0,%1}, [%2];"
                 : "=r"(r[0]), "=r"(r[1]) : "r"(addr));
}
__device__ __forceinline__ void ldsm2t(uint32_t* r, uint32_t addr) {
    asm volatile("ldmatrix.sync.aligned.m8n8.x2.trans.shared.b16 {%0,%1}, [%2];"
                 : "=r"(r[0]), "=r"(r[1]) : "r"(addr));
}
__device__ __forceinline__ void cpa16(uint32_t s, const void* g) {
    asm volatile("cp.async.cg.shared.global [%0], [%1], 16;\n" :: "r"(s), "l"(g) : "memory");
}
#define CP_COMMIT() asm volatile("cp.async.commit_group;\n" ::: "memory")
#define CP_WAIT(n)  asm volatile("cp.async.wait_group %0;\n" :: "n"(n) : "memory")

// ---------------- fp32 -> fp16 conversion ----------------------------------
__global__ __launch_bounds__(256)
void f2h_kernel(const float* __restrict__ in, __half* __restrict__ out, int n8)
{
    const int i = blockIdx.x * 256 + threadIdx.x;
    if (i < n8) {
        const float4 a = reinterpret_cast<const float4*>(in)[2 * i];
        const float4 b = reinterpret_cast<const float4*>(in)[2 * i + 1];
        reinterpret_cast<uint4*>(out)[i] =
            make_uint4(pkh2(a.x, a.y), pkh2(a.z, a.w), pkh2(b.x, b.y), pkh2(b.z, b.w));
    }
}

// ---------------- FP16 GEMM with cp.async 3-stage pipeline ------------------
// C[M,N] = A[M,K] @ W[N,K]^T + bias (+gelu).  A,W fp16; C fp32 or fp16.
// BM in {64,128}, BN=128, BK=32. 256 threads = 8 warps, warp tile (BM/2)x32.
// blockIdx.z selects among up to 3 (W,bias,C) triples sharing the same A.
template<int GELU, int BM, int OUT16>
__global__ __launch_bounds__(256)
void gemm_a16(int K, int N, const __half* __restrict__ A,
              const __half* __restrict__ W0, const float* __restrict__ b0, void* __restrict__ C0,
              const __half* __restrict__ W1_, const float* __restrict__ b1, void* __restrict__ C1,
              const __half* __restrict__ W2_, const float* __restrict__ b2, void* __restrict__ C2)
{
    constexpr int MI  = BM / 32;        // m16 tiles per warp
    constexpr int LDH = 40;             // halves per smem row (80B stride)
    constexpr int SH  = (BM + 128) * LDH;  // halves per stage
    extern __shared__ __align__(16) char smem_raw[];
    const uint32_t sm_base = (uint32_t)__cvta_generic_to_shared(smem_raw);

    const int z = blockIdx.z;
    const __half* W   = (z == 0) ? W0 : (z == 1) ? W1_ : W2_;
    const float*  bia = (z == 0) ? b0 : (z == 1) ? b1  : b2;
    void*         C   = (z == 0) ? C0 : (z == 1) ? C1  : C2;

    const int tid  = threadIdx.x;
    const int lane = tid & 31;
    const int wid  = tid >> 5;
    const int wm   = (wid >> 2) * (BM / 2);
    const int wn   = (wid & 3) * 32;
    const int l4   = lane >> 2;
    const int lm   = lane & 3;

    const __half* Ag = A + (size_t)blockIdx.y * BM * K;
    const __half* Wg = W + (size_t)blockIdx.x * 128 * K;

    const int rA0 = tid >> 2,         kA0 = (tid & 3) * 8;
    const int rB1 = (tid + 256) >> 2;

    // ldmatrix source mapping
    const int rA  = (lane & 7) + ((lane >> 3) & 1) * 8;
    const int kA  = (lane >> 4) * 8;
    const int lB  = lane & 15;
    const int rB  = lB & 7;
    const int kB  = (lB >> 3) * 8;
    const uint32_t aRowOfs = (uint32_t)((wm + rA) * LDH + kA);
    const uint32_t bRowOfs = (uint32_t)((wn + rB) * LDH + kB);

    float acc[MI][4][4];
    #pragma unroll
    for (int i = 0; i < MI; ++i)
        #pragma unroll
        for (int j = 0; j < 4; ++j)
            #pragma unroll
            for (int r = 0; r < 4; ++r) acc[i][j][r] = 0.f;

    auto issue = [&](int st, int k0) {
        const uint32_t sb = sm_base + (uint32_t)(st * SH) * 2;
        cpa16(sb + (uint32_t)(rA0 * LDH + kA0) * 2, Ag + (size_t)rA0 * K + k0 + kA0);
        if (BM == 128)
            cpa16(sb + (uint32_t)(rB1 * LDH + kA0) * 2, Ag + (size_t)rB1 * K + k0 + kA0);
        cpa16(sb + (uint32_t)((BM + rA0) * LDH + kA0) * 2, Wg + (size_t)rA0 * K + k0 + kA0);
        cpa16(sb + (uint32_t)((BM + rB1) * LDH + kA0) * 2, Wg + (size_t)rB1 * K + k0 + kA0);
        CP_COMMIT();
    };
    auto compute = [&](int st) {
        const uint32_t abuf = sm_base + (uint32_t)(st * SH) * 2;
        const uint32_t bbuf = abuf + (uint32_t)(BM * LDH) * 2;
        #pragma unroll
        for (int ks = 0; ks < 2; ++ks) {
            uint32_t af[MI][4], bfr[4][2];
            #pragma unroll
            for (int i = 0; i < MI; ++i)
                ldsm4(af[i], abuf + (aRowOfs + (uint32_t)(i * 16 * LDH + ks * 16)) * 2);
            #pragma unroll
            for (int j = 0; j < 4; ++j)
                ldsm2(bfr[j], bbuf + (bRowOfs + (uint32_t)(j * 8 * LDH + ks * 16)) * 2);
            #pragma unroll
            for (int i = 0; i < MI; ++i)
                #pragma unroll
                for (int j = 0; j < 4; ++j)
                    mma_f16(acc[i][j], af[i], bfr[j]);
        }
    };

    issue(0, 0);
    issue(1, 32);
    const int nk = K / 32;
    for (int i = 0; i < nk; ++i) {
        CP_WAIT(1);
        __syncthreads();
        const int nx = i + 2;
        if (nx < nk) issue(nx - (nx >= 3 ? 3 : 0) - (nx >= 6 ? 0 : 0) >= 0 ? (nx % 3) : 0, nx * 32);
        compute(i % 3);
    }

    #pragma unroll
    for (int i = 0; i < MI; ++i) {
        const int row = blockIdx.y * BM + wm + i * 16 + l4;
        #pragma unroll
        for (int j = 0; j < 4; ++j) {
            const int col = blockIdx.x * 128 + wn + j * 8 + lm * 2;
            const float bv0 = bia[col], bv1 = bia[col + 1];
            float v0 = acc[i][j][0] + bv0;
            float v1 = acc[i][j][1] + bv1;
            float v2 = acc[i][j][2] + bv0;
            float v3 = acc[i][j][3] + bv1;
            if (GELU) {
                v0 = 0.5f * v0 * (1.f + erff(v0 * 0.70710678118654752f));
                v1 = 0.5f * v1 * (1.f + erff(v1 * 0.70710678118654752f));
                v2 = 0.5f * v2 * (1.f + erff(v2 * 0.70710678118654752f));
                v3 = 0.5f * v3 * (1.f + erff(v3 * 0.70710678118654752f));
            }
            if (OUT16) {
                __half* Ch = (__half*)C;
                *reinterpret_cast<uint32_t*>(Ch + (size_t)row * N + col)       = pkh2(v0, v1);
                *reinterpret_cast<uint32_t*>(Ch + (size_t)(row + 8) * N + col) = pkh2(v2, v3);
            } else {
                float* Cf = (float*)C;
                *reinterpret_cast<float2*>(Cf + (size_t)row * N + col)       = make_float2(v0, v1);
                *reinterpret_cast<float2*>(Cf + (size_t)(row + 8) * N + col) = make_float2(v2, v3);
            }
        }
    }
}

// ---------------- Attention: FA2-style fp16 MMA, fp16 I/O -------------------
#define AT_LDH 72   // halves per smem row (144B): ldmatrix phases conflict-free
__global__ __launch_bounds__(128)
void attn_f16(const __half* __restrict__ q,
              const __half* __restrict__ k,
              const __half* __restrict__ v,
              const float* __restrict__ mask,
              __half* __restrict__ out)
{
    __shared__ __half Ks[64][AT_LDH];
    __shared__ __half Vs[64][AT_LDH];
    __shared__ float  msk[64];

    const int b    = blockIdx.z;
    const int h    = blockIdx.y;
    const int q0   = blockIdx.x * 64;
    const int tid  = threadIdx.x;
    const int w    = tid >> 5;
    const int lane = tid & 31;
    const int g    = lane >> 2;
    const int tg   = lane & 3;
    const int lB   = lane & 15;
    const int rBk  = lB & 7;
    const int kBk  = (lB >> 3) * 8;

    const size_t boff = (size_t)b * SS;
    const int hofs = h * HD;
    const int rlo  = q0 + w * 16 + g;

    const uint32_t ks_base = (uint32_t)__cvta_generic_to_shared(&Ks[0][0]);
    const uint32_t vs_base = (uint32_t)__cvta_generic_to_shared(&Vs[0][0]);

    // Q fragments, pre-scaled by 1/8 (exact power-of-two scale in fp16)
    uint32_t qa[4][4];
    {
        const __half* qlo = q + (boff + rlo) * DD + hofs;
        const __half* qhi = qlo + 8 * DD;
        const __half2 s = __float2half2_rn(0.125f);
        #pragma unroll
        for (int ks = 0; ks < 4; ++ks) {
            const int c0 = ks * 16 + 2 * tg;
            __half2 t0 = __hmul2(*reinterpret_cast<const __half2*>(qlo + c0), s);
            __half2 t1 = __hmul2(*reinterpret_cast<const __half2*>(qhi + c0), s);
            __half2 t2 = __hmul2(*reinterpret_cast<const __half2*>(qlo + c0 + 8), s);
            __half2 t3 = __hmul2(*reinterpret_cast<const __half2*>(qhi + c0 + 8), s);
            qa[ks][0] = *reinterpret_cast<uint32_t*>(&t0);
            qa[ks][1] = *reinterpret_cast<uint32_t*>(&t1);
            qa[ks][2] = *reinterpret_cast<uint32_t*>(&t2);
            qa[ks][3] = *reinterpret_cast<uint32_t*>(&t3);
        }
    }

    float o[8][4];
    #pragma unroll
    for (int j = 0; j < 8; ++j)
        #pragma unroll
        for (int r = 0; r < 4; ++r) o[j][r] = 0.f;
    float mx_lo = -1e30f, mx_hi = -1e30f, l_lo = 0.f, l_hi = 0.f;

    for (int kt = 0; kt < SS; kt += 64) {
        __syncthreads();
        // stage K,V tiles via cp.async (fp16 direct, 4+4 16B chunks per thread)
        #pragma unroll
        for (int it = 0; it < 4; ++it) {
            const int c  = it * 128 + tid;
            const int r  = c >> 3, cc = (c & 7) * 8;
            const size_t gofs = (boff + kt + r) * DD + hofs + cc;
            cpa16(ks_base + (uint32_t)(r * AT_LDH + cc) * 2, k + gofs);
            cpa16(vs_base + (uint32_t)(r * AT_LDH + cc) * 2, v + gofs);
        }
        CP_COMMIT();
        if (tid < 64) msk[tid] = -10000.f * (1.f - mask[boff + kt + tid]);
        CP_WAIT(0);
        __syncthreads();

        // ---- scores S[16q x 64k] per warp ----
        float sc[8][4];
        #pragma unroll
        for (int j = 0; j < 8; ++j) {
            sc[j][0] = sc[j][1] = sc[j][2] = sc[j][3] = 0.f;
            #pragma unroll
            for (int ks = 0; ks < 4; ++ks) {
                uint32_t bb[2];
                ldsm2(bb, ks_base + (uint32_t)((j * 8 + rBk) * AT_LDH + kBk + ks * 16) * 2);
                mma_f16(sc[j], qa[ks], bb);
            }
        }

        // ---- online softmax ----
        float nm_lo = mx_lo, nm_hi = mx_hi;
        #pragma unroll
        for (int j = 0; j < 8; ++j) {
            const float m0 = msk[j * 8 + 2 * tg], m1 = msk[j * 8 + 2 * tg + 1];
            sc[j][0] += m0; sc[j][1] += m1; sc[j][2] += m0; sc[j][3] += m1;
            nm_lo = fmaxf(nm_lo, fmaxf(sc[j][0], sc[j][1]));
            nm_hi = fmaxf(nm_hi, fmaxf(sc[j][2], sc[j][3]));
        }
        nm_lo = fmaxf(nm_lo, __shfl_xor_sync(0xFFFFFFFFu, nm_lo, 1));
        nm_lo = fmaxf(nm_lo, __shfl_xor_sync(0xFFFFFFFFu, nm_lo, 2));
        nm_hi = fmaxf(nm_hi, __shfl_xor_sync(0xFFFFFFFFu, nm_hi, 1));
        nm_hi = fmaxf(nm_hi, __shfl_xor_sync(0xFFFFFFFFu, nm_hi, 2));
        const float cor_lo = __expf(mx_lo - nm_lo);
        const float cor_hi = __expf(mx_hi - nm_hi);
        mx_lo = nm_lo; mx_hi = nm_hi;

        uint32_t pa[4][4];
        float sl_lo = 0.f, sl_hi = 0.f;
        #pragma unroll
        for (int j = 0; j < 8; ++j) {
            const float p0 = __expf(sc[j][0] - mx_lo);
            const float p1 = __expf(sc[j][1] - mx_lo);
            const float p2 = __expf(sc[j][2] - mx_hi);
            const float p3 = __expf(sc[j][3] - mx_hi);
            sl_lo += p0 + p1; sl_hi += p2 + p3;
            const int ks = j >> 1;
            if ((j & 1) == 0) {
                pa[ks][0] = pkh2(p0, p1);
                pa[ks][1] = pkh2(p2, p3);
            } else {
                pa[ks][2] = pkh2(p0, p1);
                pa[ks][3] = pkh2(p2, p3);
            }
        }
        sl_lo += __shfl_xor_sync(0xFFFFFFFFu, sl_lo, 1);
        sl_lo += __shfl_xor_sync(0xFFFFFFFFu, sl_lo, 2);
        sl_hi += __shfl_xor_sync(0xFFFFFFFFu, sl_hi, 1);
        sl_hi += __shfl_xor_sync(0xFFFFFFFFu, sl_hi, 2);
        l_lo = l_lo * cor_lo + sl_lo;
        l_hi = l_hi * cor_hi + sl_hi;
        #pragma unroll
        for (int j = 0; j < 8; ++j) {
            o[j][0] *= cor_lo; o[j][1] *= cor_lo;
            o[j][2] *= cor_hi; o[j][3] *= cor_hi;
        }

        // ---- PV ----
        #pragma unroll
        for (int ks = 0; ks < 4; ++ks) {
            #pragma unroll
            for (int j = 0; j < 8; ++j) {
                uint32_t bv[2];
                ldsm2t(bv, vs_base + (uint32_t)((ks * 16 + lB) * AT_LDH + j * 8) * 2);
                mma_f16(o[j], pa[ks], bv);
            }
        }
    }

    const float inv_lo = 1.f / l_lo;
    const float inv_hi = 1.f / l_hi;
    __half* olo = out + (boff + rlo) * DD + hofs;
    __half* ohi = olo + 8 * DD;
    #pragma unroll
    for (int j = 0; j < 8; ++j) {
        *reinterpret_cast<uint32_t*>(olo + j * 8 + 2 * tg) =
            pkh2(o[j][0] * inv_lo, o[j][1] * inv_lo);
        *reinterpret_cast<uint32_t*>(ohi + j * 8 + 2 * tg) =
            pkh2(o[j][2] * inv_hi, o[j][3] * inv_hi);
    }
}

// ---------------- Fused residual-add + LayerNorm ---------------------------
// OUT16: additionally write an fp16 copy (input for the next GEMM).
template<int OUT16>
__global__ __launch_bounds__(256)
void ln_kernel(const float* __restrict__ a, const float* __restrict__ r,
               const float* __restrict__ gamma, const float* __restrict__ beta,
               float* __restrict__ out, __half* __restrict__ out16)
{
    const size_t base = (size_t)blockIdx.x * DD;
    const int t = threadIdx.x;

    const float v0 = a[base + t]       + r[base + t];
    const float v1 = a[base + t + 256] + r[base + t + 256];
    const float v2 = a[base + t + 512] + r[base + t + 512];

    float s  = v0 + v1 + v2;
    float ss = v0 * v0 + v1 * v1 + v2 * v2;
    #pragma unroll
    for (int o = 16; o > 0; o >>= 1) {
        s  += __shfl_xor_sync(0xFFFFFFFFu, s,  o);
        ss += __shfl_xor_sync(0xFFFFFFFFu, ss, o);
    }
    __shared__ float rs[8], rss[8], stats[2];
    const int wid = t >> 5, lid = t & 31;
    if (lid == 0) { rs[wid] = s; rss[wid] = ss; }
    __syncthreads();
    if (t == 0) {
        float S = 0.f, SSq = 0.f;
        #pragma unroll
        for (int i = 0; i < 8; ++i) { S += rs[i]; SSq += rss[i]; }
        const float mu  = S * (1.f / DD);
        const float var = SSq * (1.f / DD) - mu * mu;
        stats[0] = mu;
        stats[1] = rsqrtf(var + 1e-12f);
    }
    __syncthreads();
    const float mu = stats[0], rstd = stats[1];

    const float o0 = gamma[t]       * (v0 - mu) * rstd + beta[t];
    const float o1 = gamma[t + 256] * (v1 - mu) * rstd + beta[t + 256];
    const float o2 = gamma[t + 512] * (v2 - mu) * rstd + beta[t + 512];
    out[base + t]       = o0;
    out[base + t + 256] = o1;
    out[base + t + 512] = o2;
    if (OUT16) {
        out16[base + t]       = __float2half(o0);
        out16[base + t + 256] = __float2half(o1);
        out16[base + t + 512] = __float2half(o2);
    }
}

// ---------------- launcher -------------------------------------------------
extern "C" void kernel_launch(void* const* d_in, const int* in_sizes, int n_in,
                              void* d_out, int out_size)
{
    const float* x    = (const float*)d_in[0];
    const float* mask = (const float*)d_in[1];
    const float* Wq   = (const float*)d_in[2];
    const float* bq   = (const float*)d_in[3];
    const float* Wk   = (const float*)d_in[4];
    const float* bk   = (const float*)d_in[5];
    const float* Wv   = (const float*)d_in[6];
    const float* bv   = (const float*)d_in[7];
    const float* Wp   = (const float*)d_in[8];
    const float* bp   = (const float*)d_in[9];
    const float* g1   = (const float*)d_in[10];
    const float* be1  = (const float*)d_in[11];
    const float* W1   = (const float*)d_in[12];
    const float* bf1  = (const float*)d_in[13];
    const float* W2   = (const float*)d_in[14];
    const float* bf2  = (const float*)d_in[15];
    const float* g2   = (const float*)d_in[16];
    const float* be2  = (const float*)d_in[17];
    float* outp = (float*)d_out;

    __half *phx, *phwq, *phwk, *phwv, *phwp, *phw1, *phw2;
    __half *phq, *phk, *phv, *phat, *phx1, *phff;
    float *pproj, *px1f, *pff2;
    cudaGetSymbolAddress((void**)&phx,  h_x);
    cudaGetSymbolAddress((void**)&phwq, h_wq);
    cudaGetSymbolAddress((void**)&phwk, h_wk);
    cudaGetSymbolAddress((void**)&phwv, h_wv);
    cudaGetSymbolAddress((void**)&phwp, h_wp);
    cudaGetSymbolAddress((void**)&phw1, h_w1);
    cudaGetSymbolAddress((void**)&phw2, h_w2);
    cudaGetSymbolAddress((void**)&phq,  h_q);
    cudaGetSymbolAddress((void**)&phk,  h_k);
    cudaGetSymbolAddress((void**)&phv,  h_v);
    cudaGetSymbolAddress((void**)&phat, h_at);
    cudaGetSymbolAddress((void**)&phx1, h_x1);
    cudaGetSymbolAddress((void**)&phff, h_ff);
    cudaGetSymbolAddress((void**)&pproj, g_proj);
    cudaGetSymbolAddress((void**)&px1f,  g_x1f);
    cudaGetSymbolAddress((void**)&pff2,  g_ff2);

    // dynamic smem sizes: 3 stages * (BM+128)*40 halves * 2B
    const int smem128 = 3 * (128 + 128) * 40 * 2;  // 61440
    const int smem64  = 3 * (64 + 128) * 40 * 2;   // 46080
    cudaFuncSetAttribute(gemm_a16<0, 128, 1>, cudaFuncAttributeMaxDynamicSharedMemorySize, smem128);
    cudaFuncSetAttribute(gemm_a16<1, 128, 1>, cudaFuncAttributeMaxDynamicSharedMemorySize, smem128);
    cudaFuncSetAttribute(gemm_a16<0, 64, 0>,  cudaFuncAttributeMaxDynamicSharedMemorySize, smem64);

    // fp32 -> fp16 conversions (inputs + weights)
    auto cvt = [&](const float* src, __half* dst, int n) {
        const int n8 = n / 8;
        f2h_kernel<<<(n8 + 255) / 256, 256>>>(src, dst, n8);
    };
    cvt(x,  phx,  MM * DD);
    cvt(Wq, phwq, DD * DD);
    cvt(Wk, phwk, DD * DD);
    cvt(Wv, phwv, DD * DD);
    cvt(Wp, phwp, DD * DD);
    cvt(W1, phw1, DFF * DD);
    cvt(W2, phw2, DD * DFF);

    const dim3 blk(256);

    // QKV projections (one launch, z selects W/bias/out)
    gemm_a16<0, 128, 1><<<dim3(DD / 128, MM / 128, 3), blk, smem128>>>(
        DD, DD, phx, phwq, bq, phq, phwk, bk, phk, phwv, bv, phv);

    // Attention (fp16 in/out)
    attn_f16<<<dim3(SS / 64, HH, BB), 128>>>(phq, phk, phv, mask, phat);

    // Output projection (fp32 out) + residual + LN1 (fp32 + fp16 copies)
    gemm_a16<0, 64, 0><<<dim3(DD / 128, MM / 64, 1), blk, smem64>>>(
        DD, DD, phat, phwp, bp, pproj, phwp, bp, pproj, phwp, bp, pproj);
    ln_kernel<1><<<MM, 256>>>(x, pproj, g1, be1, px1f, phx1);

    // FFN
    gemm_a16<1, 128, 1><<<dim3(DFF / 128, MM / 128, 1), blk, smem128>>>(
        DD, DFF, phx1, phw1, bf1, phff, phw1, bf1, phff, phw1, bf1, phff);
    gemm_a16<0, 64, 0><<<dim3(DD / 128, MM / 64, 1), blk, smem64>>>(
        DFF, DD, phff, phw2, bf2, pff2, phw2, bf2, pff2, phw2, bf2, pff2);

    // Residual + LN2 -> output (fp32 only)
    ln_kernel<0><<<MM, 256>>>(px1f, pff2, g2, be2, outp, nullptr);
}

// round 10
// speedup vs baseline: 7.9933x; 1.0384x over previous
#include <cuda_runtime.h>
#include <cuda_bf16.h>
#include <cuda_fp16.h>
#include <math.h>
#include <stdint.h>

// Problem dims (fixed by dataset)
#define BB 2
#define SS 2048
#define DD 768
#define HH 12
#define HD 64
#define DFF 3072
#define MM (BB * SS)   // 4096 tokens

// ---------------- scratch (no allocations allowed) ----------------
__device__ __align__(16) __half h_x [MM * DD];
__device__ __align__(16) __half h_wq[DD * DD];
__device__ __align__(16) __half h_wk[DD * DD];
__device__ __align__(16) __half h_wv[DD * DD];
__device__ __align__(16) __half h_wp[DD * DD];
__device__ __align__(16) __half h_w1[DFF * DD];
__device__ __align__(16) __half h_w2[DD * DFF];
__device__ __align__(16) __half h_q [MM * DD];
__device__ __align__(16) __half h_k [MM * DD];
__device__ __align__(16) __half h_v [MM * DD];
__device__ __align__(16) __half h_at[MM * DD];
__device__ __align__(16) __half h_x1[MM * DD];
__device__ __align__(16) __half h_ff[MM * DFF];
__device__ __align__(16) float  g_proj[MM * DD];
__device__ __align__(16) float  g_x1f [MM * DD];
__device__ __align__(16) float  g_ff2 [MM * DD];

// ---------------- helpers --------------------------------------------------
__device__ __forceinline__ uint32_t pkh2(float x, float y) {
    __half2 h = __floats2half2_rn(x, y);
    return *reinterpret_cast<uint32_t*>(&h);
}
__device__ __forceinline__ void mma_f16(float* c, const uint32_t* a, const uint32_t* b) {
    asm volatile(
        "mma.sync.aligned.m16n8k16.row.col.f32.f16.f16.f32 "
        "{%0,%1,%2,%3},{%4,%5,%6,%7},{%8,%9},{%0,%1,%2,%3};\n"
        : "+f"(c[0]), "+f"(c[1]), "+f"(c[2]), "+f"(c[3])
        : "r"(a[0]), "r"(a[1]), "r"(a[2]), "r"(a[3]), "r"(b[0]), "r"(b[1]));
}
__device__ __forceinline__ void ldsm4(uint32_t* r, uint32_t addr) {
    asm volatile("ldmatrix.sync.aligned.m8n8.x4.shared.b16 {%0,%1,%2,%3}, [%4];"
                 : "=r"(r[0]), "=r"(r[1]), "=r"(r[2]), "=r"(r[3]) : "r"(addr));
}
__device__ __forceinline__ void ldsm2(uint32_t* r, uint32_t addr) {
    asm volatile("ldmatrix.sync.aligned.m8n8.x2.shared.b16 {%0,%1}, [%2];"
                 : "=r"(r[0]), "=r"(r[1]) : "r"(addr));
}
__device__ __forceinline__ void ldsm2t(uint32_t* r, uint32_t addr) {
    asm volatile("ldmatrix.sync.aligned.m8n8.x2.trans.shared.b16 {%0,%1}, [%2];"
                 : "=r"(r[0]), "=r"(r[1]) : "r"(addr));
}
__device__ __forceinline__ void cpa16(uint32_t s, const void* g) {
    asm volatile("cp.async.cg.shared.global [%0], [%1], 16;\n" :: "r"(s), "l"(g) : "memory");
}
#define CP_COMMIT() asm volatile("cp.async.commit_group;\n" ::: "memory")
#define CP_WAIT(n)  asm volatile("cp.async.wait_group %0;\n" :: "n"(n) : "memory")

// ---------------- fused fp32 -> fp16 conversion (one launch) ----------------
struct CvtArgs {
    const float* src[7];
    __half*      dst[7];
    int          cum[8];   // prefix sums of n/8 per tensor
};
__global__ __launch_bounds__(256)
void f2h_multi(CvtArgs a)
{
    const int idx = blockIdx.x * 256 + threadIdx.x;
    if (idx >= a.cum[7]) return;
    int seg = 0;
    #pragma unroll
    for (int j = 1; j < 7; ++j) seg += (idx >= a.cum[j]) ? 1 : 0;
    const int i = idx - a.cum[seg];
    const float4 lo = reinterpret_cast<const float4*>(a.src[seg])[2 * i];
    const float4 hi = reinterpret_cast<const float4*>(a.src[seg])[2 * i + 1];
    reinterpret_cast<uint4*>(a.dst[seg])[i] =
        make_uint4(pkh2(lo.x, lo.y), pkh2(lo.z, lo.w), pkh2(hi.x, hi.y), pkh2(hi.z, hi.w));
}

// ---------------- FP16 GEMM with cp.async 3-stage pipeline ------------------
// C[M,N] = A[M,K] @ W[N,K]^T + bias (+gelu).  A,W fp16; C fp32 or fp16.
// BM in {64,128}, BN=128, BK=32. 256 threads = 8 warps, warp tile (BM/2)x32.
// blockIdx.z selects among up to 3 (W,bias,C) triples sharing the same A.
template<int GELU, int BM, int OUT16>
__global__ __launch_bounds__(256)
void gemm_a16(int K, int N, const __half* __restrict__ A,
              const __half* __restrict__ W0, const float* __restrict__ b0, void* __restrict__ C0,
              const __half* __restrict__ W1_, const float* __restrict__ b1, void* __restrict__ C1,
              const __half* __restrict__ W2_, const float* __restrict__ b2, void* __restrict__ C2)
{
    constexpr int MI  = BM / 32;           // m16 tiles per warp
    constexpr int LDH = 40;                // halves per smem row (80B stride)
    constexpr int SH  = (BM + 128) * LDH;  // halves per stage
    extern __shared__ __align__(16) char smem_raw[];
    const uint32_t sm_base = (uint32_t)__cvta_generic_to_shared(smem_raw);

    const int z = blockIdx.z;
    const __half* W   = (z == 0) ? W0 : (z == 1) ? W1_ : W2_;
    const float*  bia = (z == 0) ? b0 : (z == 1) ? b1  : b2;
    void*         C   = (z == 0) ? C0 : (z == 1) ? C1  : C2;

    const int tid  = threadIdx.x;
    const int lane = tid & 31;
    const int wid  = tid >> 5;
    const int wm   = (wid >> 2) * (BM / 2);
    const int wn   = (wid & 3) * 32;
    const int l4   = lane >> 2;
    const int lm   = lane & 3;

    const __half* Ag = A + (size_t)blockIdx.y * BM * K;
    const __half* Wg = W + (size_t)blockIdx.x * 128 * K;

    const int rA0 = tid >> 2,         kA0 = (tid & 3) * 8;
    const int rB1 = (tid + 256) >> 2;

    // ldmatrix source mapping
    const int rA  = (lane & 7) + ((lane >> 3) & 1) * 8;
    const int kA  = (lane >> 4) * 8;
    const int lB  = lane & 15;
    const int rB  = lB & 7;
    const int kB  = (lB >> 3) * 8;
    const uint32_t aRowOfs = (uint32_t)((wm + rA) * LDH + kA);
    const uint32_t bRowOfs = (uint32_t)((wn + rB) * LDH + kB);

    float acc[MI][4][4];
    #pragma unroll
    for (int i = 0; i < MI; ++i)
        #pragma unroll
        for (int j = 0; j < 4; ++j)
            #pragma unroll
            for (int r = 0; r < 4; ++r) acc[i][j][r] = 0.f;

    auto issue = [&](int st, int k0) {
        const uint32_t sb = sm_base + (uint32_t)(st * SH) * 2;
        cpa16(sb + (uint32_t)(rA0 * LDH + kA0) * 2, Ag + (size_t)rA0 * K + k0 + kA0);
        if (BM == 128)
            cpa16(sb + (uint32_t)(rB1 * LDH + kA0) * 2, Ag + (size_t)rB1 * K + k0 + kA0);
        cpa16(sb + (uint32_t)((BM + rA0) * LDH + kA0) * 2, Wg + (size_t)rA0 * K + k0 + kA0);
        cpa16(sb + (uint32_t)((BM + rB1) * LDH + kA0) * 2, Wg + (size_t)rB1 * K + k0 + kA0);
        CP_COMMIT();
    };
    auto compute = [&](int st) {
        const uint32_t abuf = sm_base + (uint32_t)(st * SH) * 2;
        const uint32_t bbuf = abuf + (uint32_t)(BM * LDH) * 2;
        #pragma unroll
        for (int ks = 0; ks < 2; ++ks) {
            uint32_t af[MI][4], bfr[4][2];
            #pragma unroll
            for (int i = 0; i < MI; ++i)
                ldsm4(af[i], abuf + (aRowOfs + (uint32_t)(i * 16 * LDH + ks * 16)) * 2);
            #pragma unroll
            for (int j = 0; j < 4; ++j)
                ldsm2(bfr[j], bbuf + (bRowOfs + (uint32_t)(j * 8 * LDH + ks * 16)) * 2);
            #pragma unroll
            for (int i = 0; i < MI; ++i)
                #pragma unroll
                for (int j = 0; j < 4; ++j)
                    mma_f16(acc[i][j], af[i], bfr[j]);
        }
    };

    issue(0, 0);
    issue(1, 32);
    const int nk = K / 32;
    for (int i = 0; i < nk; ++i) {
        if (i + 1 < nk) { CP_WAIT(1); } else { CP_WAIT(0); }   // exact wait: tile i ready
        __syncthreads();
        const int nx = i + 2;
        if (nx < nk) issue(nx % 3, nx * 32);
        compute(i % 3);
    }

    #pragma unroll
    for (int i = 0; i < MI; ++i) {
        const int row = blockIdx.y * BM + wm + i * 16 + l4;
        #pragma unroll
        for (int j = 0; j < 4; ++j) {
            const int col = blockIdx.x * 128 + wn + j * 8 + lm * 2;
            const float bv0 = bia[col], bv1 = bia[col + 1];
            float v0 = acc[i][j][0] + bv0;
            float v1 = acc[i][j][1] + bv1;
            float v2 = acc[i][j][2] + bv0;
            float v3 = acc[i][j][3] + bv1;
            if (GELU) {
                v0 = 0.5f * v0 * (1.f + erff(v0 * 0.70710678118654752f));
                v1 = 0.5f * v1 * (1.f + erff(v1 * 0.70710678118654752f));
                v2 = 0.5f * v2 * (1.f + erff(v2 * 0.70710678118654752f));
                v3 = 0.5f * v3 * (1.f + erff(v3 * 0.70710678118654752f));
            }
            if (OUT16) {
                __half* Ch = (__half*)C;
                *reinterpret_cast<uint32_t*>(Ch + (size_t)row * N + col)       = pkh2(v0, v1);
                *reinterpret_cast<uint32_t*>(Ch + (size_t)(row + 8) * N + col) = pkh2(v2, v3);
            } else {
                float* Cf = (float*)C;
                *reinterpret_cast<float2*>(Cf + (size_t)row * N + col)       = make_float2(v0, v1);
                *reinterpret_cast<float2*>(Cf + (size_t)(row + 8) * N + col) = make_float2(v2, v3);
            }
        }
    }
}

// ---------------- Attention: FA2-style fp16 MMA, double-buffered K/V --------
#define AT_LDH 72   // halves per smem row (144B): ldmatrix phases conflict-free
__global__ __launch_bounds__(128)
void attn_f16(const __half* __restrict__ q,
              const __half* __restrict__ k,
              const __half* __restrict__ v,
              const float* __restrict__ mask,
              __half* __restrict__ out)
{
    __shared__ __half Ks[2][64][AT_LDH];
    __shared__ __half Vs[2][64][AT_LDH];
    __shared__ float  msk[2][64];

    const int b    = blockIdx.z;
    const int h    = blockIdx.y;
    const int q0   = blockIdx.x * 64;
    const int tid  = threadIdx.x;
    const int w    = tid >> 5;
    const int lane = tid & 31;
    const int g    = lane >> 2;
    const int tg   = lane & 3;
    const int lB   = lane & 15;
    const int rBk  = lB & 7;
    const int kBk  = (lB >> 3) * 8;

    const size_t boff = (size_t)b * SS;
    const int hofs = h * HD;
    const int rlo  = q0 + w * 16 + g;

    const uint32_t ks0 = (uint32_t)__cvta_generic_to_shared(&Ks[0][0][0]);
    const uint32_t vs0 = (uint32_t)__cvta_generic_to_shared(&Vs[0][0][0]);
    constexpr uint32_t BUFB = 64 * AT_LDH * 2;   // bytes per K (or V) buffer

    // stage tile t into buffer t&1 (cp.async for K/V, normal store for mask)
    auto issue = [&](int t) {
        const int kt = t * 64;
        const uint32_t bo = (uint32_t)(t & 1) * BUFB;
        #pragma unroll
        for (int it = 0; it < 4; ++it) {
            const int c  = it * 128 + tid;
            const int r  = c >> 3, cc = (c & 7) * 8;
            const size_t gofs = (boff + kt + r) * DD + hofs + cc;
            cpa16(ks0 + bo + (uint32_t)(r * AT_LDH + cc) * 2, k + gofs);
            cpa16(vs0 + bo + (uint32_t)(r * AT_LDH + cc) * 2, v + gofs);
        }
        CP_COMMIT();
        if (tid < 64) msk[t & 1][tid] = -10000.f * (1.f - mask[boff + kt + tid]);
    };

    uint32_t qa[4][4];
    {
        const __half* qlo = q + (boff + rlo) * DD + hofs;
        const __half* qhi = qlo + 8 * DD;
        const __half2 s = __float2half2_rn(0.125f);
        #pragma unroll
        for (int ks = 0; ks < 4; ++ks) {
            const int c0 = ks * 16 + 2 * tg;
            __half2 t0 = __hmul2(*reinterpret_cast<const __half2*>(qlo + c0), s);
            __half2 t1 = __hmul2(*reinterpret_cast<const __half2*>(qhi + c0), s);
            __half2 t2 = __hmul2(*reinterpret_cast<const __half2*>(qlo + c0 + 8), s);
            __half2 t3 = __hmul2(*reinterpret_cast<const __half2*>(qhi + c0 + 8), s);
            qa[ks][0] = *reinterpret_cast<uint32_t*>(&t0);
            qa[ks][1] = *reinterpret_cast<uint32_t*>(&t1);
            qa[ks][2] = *reinterpret_cast<uint32_t*>(&t2);
            qa[ks][3] = *reinterpret_cast<uint32_t*>(&t3);
        }
    }

    float o[8][4];
    #pragma unroll
    for (int j = 0; j < 8; ++j)
        #pragma unroll
        for (int r = 0; r < 4; ++r) o[j][r] = 0.f;
    float mx_lo = -1e30f, mx_hi = -1e30f, l_lo = 0.f, l_hi = 0.f;

    constexpr int NT = SS / 64;
    issue(0);

    for (int t = 0; t < NT; ++t) {
        if (t + 1 < NT) {            // overlap: stage next tile during this compute
            issue(t + 1);
            CP_WAIT(1);              // tile t complete (tile t+1 still in flight)
        } else {
            CP_WAIT(0);
        }
        __syncthreads();

        const int buf = t & 1;
        const uint32_t ks_base = ks0 + (uint32_t)buf * BUFB;
        const uint32_t vs_base = vs0 + (uint32_t)buf * BUFB;

        // ---- scores S[16q x 64k] per warp ----
        float sc[8][4];
        #pragma unroll
        for (int j = 0; j < 8; ++j) {
            sc[j][0] = sc[j][1] = sc[j][2] = sc[j][3] = 0.f;
            #pragma unroll
            for (int ks = 0; ks < 4; ++ks) {
                uint32_t bb[2];
                ldsm2(bb, ks_base + (uint32_t)((j * 8 + rBk) * AT_LDH + kBk + ks * 16) * 2);
                mma_f16(sc[j], qa[ks], bb);
            }
        }

        // ---- online softmax ----
        float nm_lo = mx_lo, nm_hi = mx_hi;
        #pragma unroll
        for (int j = 0; j < 8; ++j) {
            const float m0 = msk[buf][j * 8 + 2 * tg], m1 = msk[buf][j * 8 + 2 * tg + 1];
            sc[j][0] += m0; sc[j][1] += m1; sc[j][2] += m0; sc[j][3] += m1;
            nm_lo = fmaxf(nm_lo, fmaxf(sc[j][0], sc[j][1]));
            nm_hi = fmaxf(nm_hi, fmaxf(sc[j][2], sc[j][3]));
        }
        nm_lo = fmaxf(nm_lo, __shfl_xor_sync(0xFFFFFFFFu, nm_lo, 1));
        nm_lo = fmaxf(nm_lo, __shfl_xor_sync(0xFFFFFFFFu, nm_lo, 2));
        nm_hi = fmaxf(nm_hi, __shfl_xor_sync(0xFFFFFFFFu, nm_hi, 1));
        nm_hi = fmaxf(nm_hi, __shfl_xor_sync(0xFFFFFFFFu, nm_hi, 2));
        const float cor_lo = __expf(mx_lo - nm_lo);
        const float cor_hi = __expf(mx_hi - nm_hi);
        mx_lo = nm_lo; mx_hi = nm_hi;

        uint32_t pa[4][4];
        float sl_lo = 0.f, sl_hi = 0.f;
        #pragma unroll
        for (int j = 0; j < 8; ++j) {
            const float p0 = __expf(sc[j][0] - mx_lo);
            const float p1 = __expf(sc[j][1] - mx_lo);
            const float p2 = __expf(sc[j][2] - mx_hi);
            const float p3 = __expf(sc[j][3] - mx_hi);
            sl_lo += p0 + p1; sl_hi += p2 + p3;
            const int ks = j >> 1;
            if ((j & 1) == 0) {
                pa[ks][0] = pkh2(p0, p1);
                pa[ks][1] = pkh2(p2, p3);
            } else {
                pa[ks][2] = pkh2(p0, p1);
                pa[ks][3] = pkh2(p2, p3);
            }
        }
        sl_lo += __shfl_xor_sync(0xFFFFFFFFu, sl_lo, 1);
        sl_lo += __shfl_xor_sync(0xFFFFFFFFu, sl_lo, 2);
        sl_hi += __shfl_xor_sync(0xFFFFFFFFu, sl_hi, 1);
        sl_hi += __shfl_xor_sync(0xFFFFFFFFu, sl_hi, 2);
        l_lo = l_lo * cor_lo + sl_lo;
        l_hi = l_hi * cor_hi + sl_hi;
        #pragma unroll
        for (int j = 0; j < 8; ++j) {
            o[j][0] *= cor_lo; o[j][1] *= cor_lo;
            o[j][2] *= cor_hi; o[j][3] *= cor_hi;
        }

        // ---- PV ----
        #pragma unroll
        for (int ks = 0; ks < 4; ++ks) {
            #pragma unroll
            for (int j = 0; j < 8; ++j) {
                uint32_t bv[2];
                ldsm2t(bv, vs_base + (uint32_t)((ks * 16 + lB) * AT_LDH + j * 8) * 2);
                mma_f16(o[j], pa[ks], bv);
            }
        }
        __syncthreads();   // compute(t) done before issue(t+2) overwrites this buffer
    }

    const float inv_lo = 1.f / l_lo;
    const float inv_hi = 1.f / l_hi;
    __half* olo = out + (boff + rlo) * DD + hofs;
    __half* ohi = olo + 8 * DD;
    #pragma unroll
    for (int j = 0; j < 8; ++j) {
        *reinterpret_cast<uint32_t*>(olo + j * 8 + 2 * tg) =
            pkh2(o[j][0] * inv_lo, o[j][1] * inv_lo);
        *reinterpret_cast<uint32_t*>(ohi + j * 8 + 2 * tg) =
            pkh2(o[j][2] * inv_hi, o[j][3] * inv_hi);
    }
}

// ---------------- Fused residual-add + LayerNorm ---------------------------
template<int OUT16>
__global__ __launch_bounds__(256)
void ln_kernel(const float* __restrict__ a, const float* __restrict__ r,
               const float* __restrict__ gamma, const float* __restrict__ beta,
               float* __restrict__ out, __half* __restrict__ out16)
{
    const size_t base = (size_t)blockIdx.x * DD;
    const int t = threadIdx.x;

    const float v0 = a[base + t]       + r[base + t];
    const float v1 = a[base + t + 256] + r[base + t + 256];
    const float v2 = a[base + t + 512] + r[base + t + 512];

    float s  = v0 + v1 + v2;
    float ss = v0 * v0 + v1 * v1 + v2 * v2;
    #pragma unroll
    for (int o = 16; o > 0; o >>= 1) {
        s  += __shfl_xor_sync(0xFFFFFFFFu, s,  o);
        ss += __shfl_xor_sync(0xFFFFFFFFu, ss, o);
    }
    __shared__ float rs[8], rss[8], stats[2];
    const int wid = t >> 5, lid = t & 31;
    if (lid == 0) { rs[wid] = s; rss[wid] = ss; }
    __syncthreads();
    if (t == 0) {
        float S = 0.f, SSq = 0.f;
        #pragma unroll
        for (int i = 0; i < 8; ++i) { S += rs[i]; SSq += rss[i]; }
        const float mu  = S * (1.f / DD);
        const float var = SSq * (1.f / DD) - mu * mu;
        stats[0] = mu;
        stats[1] = rsqrtf(var + 1e-12f);
    }
    __syncthreads();
    const float mu = stats[0], rstd = stats[1];

    const float o0 = gamma[t]       * (v0 - mu) * rstd + beta[t];
    const float o1 = gamma[t + 256] * (v1 - mu) * rstd + beta[t + 256];
    const float o2 = gamma[t + 512] * (v2 - mu) * rstd + beta[t + 512];
    out[base + t]       = o0;
    out[base + t + 256] = o1;
    out[base + t + 512] = o2;
    if (OUT16) {
        out16[base + t]       = __float2half(o0);
        out16[base + t + 256] = __float2half(o1);
        out16[base + t + 512] = __float2half(o2);
    }
}

// ---------------- launcher -------------------------------------------------
extern "C" void kernel_launch(void* const* d_in, const int* in_sizes, int n_in,
                              void* d_out, int out_size)
{
    const float* x    = (const float*)d_in[0];
    const float* mask = (const float*)d_in[1];
    const float* Wq   = (const float*)d_in[2];
    const float* bq   = (const float*)d_in[3];
    const float* Wk   = (const float*)d_in[4];
    const float* bk   = (const float*)d_in[5];
    const float* Wv   = (const float*)d_in[6];
    const float* bv   = (const float*)d_in[7];
    const float* Wp   = (const float*)d_in[8];
    const float* bp   = (const float*)d_in[9];
    const float* g1   = (const float*)d_in[10];
    const float* be1  = (const float*)d_in[11];
    const float* W1   = (const float*)d_in[12];
    const float* bf1  = (const float*)d_in[13];
    const float* W2   = (const float*)d_in[14];
    const float* bf2  = (const float*)d_in[15];
    const float* g2   = (const float*)d_in[16];
    const float* be2  = (const float*)d_in[17];
    float* outp = (float*)d_out;

    __half *phx, *phwq, *phwk, *phwv, *phwp, *phw1, *phw2;
    __half *phq, *phk, *phv, *phat, *phx1, *phff;
    float *pproj, *px1f, *pff2;
    cudaGetSymbolAddress((void**)&phx,  h_x);
    cudaGetSymbolAddress((void**)&phwq, h_wq);
    cudaGetSymbolAddress((void**)&phwk, h_wk);
    cudaGetSymbolAddress((void**)&phwv, h_wv);
    cudaGetSymbolAddress((void**)&phwp, h_wp);
    cudaGetSymbolAddress((void**)&phw1, h_w1);
    cudaGetSymbolAddress((void**)&phw2, h_w2);
    cudaGetSymbolAddress((void**)&phq,  h_q);
    cudaGetSymbolAddress((void**)&phk,  h_k);
    cudaGetSymbolAddress((void**)&phv,  h_v);
    cudaGetSymbolAddress((void**)&phat, h_at);
    cudaGetSymbolAddress((void**)&phx1, h_x1);
    cudaGetSymbolAddress((void**)&phff, h_ff);
    cudaGetSymbolAddress((void**)&pproj, g_proj);
    cudaGetSymbolAddress((void**)&px1f,  g_x1f);
    cudaGetSymbolAddress((void**)&pff2,  g_ff2);

    // dynamic smem sizes: 3 stages * (BM+128)*40 halves * 2B
    const int smem128 = 3 * (128 + 128) * 40 * 2;  // 61440
    const int smem64  = 3 * (64 + 128) * 40 * 2;   // 46080
    cudaFuncSetAttribute(gemm_a16<0, 128, 1>, cudaFuncAttributeMaxDynamicSharedMemorySize, smem128);
    cudaFuncSetAttribute(gemm_a16<1, 128, 1>, cudaFuncAttributeMaxDynamicSharedMemorySize, smem128);
    cudaFuncSetAttribute(gemm_a16<0, 64, 0>,  cudaFuncAttributeMaxDynamicSharedMemorySize, smem64);

    // single fused fp32->fp16 conversion launch (inputs + weights)
    {
        CvtArgs ca;
        const float* srcs[7] = { x, Wq, Wk, Wv, Wp, W1, W2 };
        __half*      dsts[7] = { phx, phwq, phwk, phwv, phwp, phw1, phw2 };
        const int    ns[7]   = { MM * DD, DD * DD, DD * DD, DD * DD, DD * DD,
                                 DFF * DD, DD * DFF };
        int cum = 0;
        for (int i = 0; i < 7; ++i) {
            ca.src[i] = srcs[i];
            ca.dst[i] = dsts[i];
            ca.cum[i] = cum;
            cum += ns[i] / 8;
        }
        ca.cum[7] = cum;
        f2h_multi<<<(cum + 255) / 256, 256>>>(ca);
    }

    const dim3 blk(256);

    // QKV projections (one launch, z selects W/bias/out)
    gemm_a16<0, 128, 1><<<dim3(DD / 128, MM / 128, 3), blk, smem128>>>(
        DD, DD, phx, phwq, bq, phq, phwk, bk, phk, phwv, bv, phv);

    // Attention (fp16 in/out, double-buffered K/V)
    attn_f16<<<dim3(SS / 64, HH, BB), 128>>>(phq, phk, phv, mask, phat);

    // Output projection (fp32 out) + residual + LN1 (fp32 + fp16 copies)
    gemm_a16<0, 64, 0><<<dim3(DD / 128, MM / 64, 1), blk, smem64>>>(
        DD, DD, phat, phwp, bp, pproj, phwp, bp, pproj, phwp, bp, pproj);
    ln_kernel<1><<<MM, 256>>>(x, pproj, g1, be1, px1f, phx1);

    // FFN
    gemm_a16<1, 128, 1><<<dim3(DFF / 128, MM / 128, 1), blk, smem128>>>(
        DD, DFF, phx1, phw1, bf1, phff, phw1, bf1, phff, phw1, bf1, phff);
    gemm_a16<0, 64, 0><<<dim3(DD / 128, MM / 64, 1), blk, smem64>>>(
        DFF, DD, phff, phw2, bf2, pff2, phw2, bf2, pff2, phw2, bf2, pff2);

    // Residual + LN2 -> output (fp32 only)
    ln_kernel<0><<<MM, 256>>>(px1f, pff2, g2, be2, outp, nullptr);
}

// round 11
// speedup vs baseline: 8.4712x; 1.0598x over previous
#include <cuda_runtime.h>
#include <cuda_bf16.h>
#include <cuda_fp16.h>
#include <math.h>
#include <stdint.h>

// Problem dims (fixed by dataset)
#define BB 2
#define SS 2048
#define DD 768
#define HH 12
#define HD 64
#define DFF 3072
#define MM (BB * SS)   // 4096 tokens

// ---------------- scratch (no allocations allowed) ----------------
__device__ __align__(16) __half h_x [MM * DD];
__device__ __align__(16) __half h_wq[DD * DD];
__device__ __align__(16) __half h_wk[DD * DD];
__device__ __align__(16) __half h_wv[DD * DD];
__device__ __align__(16) __half h_wp[DD * DD];
__device__ __align__(16) __half h_w1[DFF * DD];
__device__ __align__(16) __half h_w2[DD * DFF];
__device__ __align__(16) __half h_q [MM * DD];
__device__ __align__(16) __half h_k [MM * DD];
__device__ __align__(16) __half h_v [MM * DD];
__device__ __align__(16) __half h_at[MM * DD];
__device__ __align__(16) __half h_x1[MM * DD];
__device__ __align__(16) __half h_ff[MM * DFF];
__device__ __align__(16) float  g_pa [MM * DD];   // proj partial (K half 0)
__device__ __align__(16) float  g_pb [MM * DD];   // proj partial (K half 1)
__device__ __align__(16) float  g_x1f[MM * DD];
__device__ __align__(16) float  g_fa [MM * DD];   // ffn2 partial 0
__device__ __align__(16) float  g_fb [MM * DD];   // ffn2 partial 1

// ---------------- helpers --------------------------------------------------
__device__ __forceinline__ uint32_t pkh2(float x, float y) {
    __half2 h = __floats2half2_rn(x, y);
    return *reinterpret_cast<uint32_t*>(&h);
}
__device__ __forceinline__ void mma_f16(float* c, const uint32_t* a, const uint32_t* b) {
    asm volatile(
        "mma.sync.aligned.m16n8k16.row.col.f32.f16.f16.f32 "
        "{%0,%1,%2,%3},{%4,%5,%6,%7},{%8,%9},{%0,%1,%2,%3};\n"
        : "+f"(c[0]), "+f"(c[1]), "+f"(c[2]), "+f"(c[3])
        : "r"(a[0]), "r"(a[1]), "r"(a[2]), "r"(a[3]), "r"(b[0]), "r"(b[1]));
}
__device__ __forceinline__ void ldsm4(uint32_t* r, uint32_t addr) {
    asm volatile("ldmatrix.sync.aligned.m8n8.x4.shared.b16 {%0,%1,%2,%3}, [%4];"
                 : "=r"(r[0]), "=r"(r[1]), "=r"(r[2]), "=r"(r[3]) : "r"(addr));
}
__device__ __forceinline__ void ldsm2(uint32_t* r, uint32_t addr) {
    asm volatile("ldmatrix.sync.aligned.m8n8.x2.shared.b16 {%0,%1}, [%2];"
                 : "=r"(r[0]), "=r"(r[1]) : "r"(addr));
}
__device__ __forceinline__ void ldsm2t(uint32_t* r, uint32_t addr) {
    asm volatile("ldmatrix.sync.aligned.m8n8.x2.trans.shared.b16 {%0,%1}, [%2];"
                 : "=r"(r[0]), "=r"(r[1]) : "r"(addr));
}
__device__ __forceinline__ void cpa16(uint32_t s, const void* g) {
    asm volatile("cp.async.cg.shared.global [%0], [%1], 16;\n" :: "r"(s), "l"(g) : "memory");
}
#define CP_COMMIT() asm volatile("cp.async.commit_group;\n" ::: "memory")
#define CP_WAIT(n)  asm volatile("cp.async.wait_group %0;\n" :: "n"(n) : "memory")

// ---------------- fused fp32 -> fp16 conversion (one launch) ----------------
struct CvtArgs {
    const float* src[7];
    __half*      dst[7];
    int          cum[8];
};
__global__ __launch_bounds__(256)
void f2h_multi(CvtArgs a)
{
    const int idx = blockIdx.x * 256 + threadIdx.x;
    if (idx >= a.cum[7]) return;
    int seg = 0;
    #pragma unroll
    for (int j = 1; j < 7; ++j) seg += (idx >= a.cum[j]) ? 1 : 0;
    const int i = idx - a.cum[seg];
    const float4 lo = reinterpret_cast<const float4*>(a.src[seg])[2 * i];
    const float4 hi = reinterpret_cast<const float4*>(a.src[seg])[2 * i + 1];
    reinterpret_cast<uint4*>(a.dst[seg])[i] =
        make_uint4(pkh2(lo.x, lo.y), pkh2(lo.z, lo.w), pkh2(hi.x, hi.y), pkh2(hi.z, hi.w));
}

// ---------------- FP16 GEMM: 128x128 tile, 512 threads, 4-stage cp.async ----
// C[M,N] = A[M,K(+ofs)] @ W[N,K(+ofs)]^T (+bias)(+gelu).
// 16 warps in 4x4 grid, warp tile 32x32 (2x m16 x 4x n8).
// KSPLIT: blockIdx.z picks K half (length K, row stride LDK), raw fp32 out,
//         no bias. Otherwise blockIdx.z selects (W,bias,C) triple.
#define GSTAGES 4
#define GT_SMEM (GSTAGES * 256 * 40 * 2)   // 81920 B
template<int GELU, int OUT16, int KSPLIT>
__global__ __launch_bounds__(512, 2)
void gemm_a16(int K, int LDK, int N, const __half* __restrict__ A,
              const __half* __restrict__ W0, const float* __restrict__ b0, void* __restrict__ C0,
              const __half* __restrict__ W1_, const float* __restrict__ b1, void* __restrict__ C1,
              const __half* __restrict__ W2_, const float* __restrict__ b2, void* __restrict__ C2)
{
    constexpr int LDH = 40;           // halves per smem row (80B stride)
    constexpr int SH  = 256 * LDH;    // halves per stage (A 128 rows + W 128 rows)
    extern __shared__ __align__(16) char smem_raw[];
    const uint32_t sm_base = (uint32_t)__cvta_generic_to_shared(smem_raw);

    const int z = blockIdx.z;
    const __half* W;
    const float*  bia;
    void*         C;
    if (KSPLIT) {
        W = W0; bia = b0;
        C = (z == 0) ? C0 : C1;
    } else {
        W   = (z == 0) ? W0 : (z == 1) ? W1_ : W2_;
        bia = (z == 0) ? b0 : (z == 1) ? b1  : b2;
        C   = (z == 0) ? C0 : (z == 1) ? C1  : C2;
    }
    const int kofs = KSPLIT ? z * K : 0;

    const int tid  = threadIdx.x;
    const int lane = tid & 31;
    const int wid  = tid >> 5;
    const int wm   = (wid >> 2) * 32;
    const int wn   = (wid & 3) * 32;
    const int l4   = lane >> 2;
    const int lm   = lane & 3;

    const __half* Ag = A + (size_t)blockIdx.y * 128 * LDK + kofs;
    const __half* Wg = W + (size_t)blockIdx.x * 128 * LDK + kofs;

    // staging: 512 granules (16B) each for A and W; 1 + 1 per thread
    const int rS = tid >> 2, kS = (tid & 3) * 8;

    // ldmatrix source mapping
    const int rA  = (lane & 7) + ((lane >> 3) & 1) * 8;
    const int kA  = (lane >> 4) * 8;
    const int lB  = lane & 15;
    const int rB  = lB & 7;
    const int kB  = (lB >> 3) * 8;
    const uint32_t aRowOfs = (uint32_t)((wm + rA) * LDH + kA);
    const uint32_t bRowOfs = (uint32_t)((wn + rB) * LDH + kB);

    float acc[2][4][4];
    #pragma unroll
    for (int i = 0; i < 2; ++i)
        #pragma unroll
        for (int j = 0; j < 4; ++j)
            #pragma unroll
            for (int r = 0; r < 4; ++r) acc[i][j][r] = 0.f;

    auto issue = [&](int st, int k0) {
        const uint32_t sb = sm_base + (uint32_t)(st * SH) * 2;
        cpa16(sb + (uint32_t)(rS * LDH + kS) * 2,         Ag + (size_t)rS * LDK + k0 + kS);
        cpa16(sb + (uint32_t)((128 + rS) * LDH + kS) * 2, Wg + (size_t)rS * LDK + k0 + kS);
        CP_COMMIT();
    };
    auto compute = [&](int st) {
        const uint32_t abuf = sm_base + (uint32_t)(st * SH) * 2;
        const uint32_t bbuf = abuf + (uint32_t)(128 * LDH) * 2;
        #pragma unroll
        for (int ks = 0; ks < 2; ++ks) {
            uint32_t af[2][4], bfr[4][2];
            #pragma unroll
            for (int i = 0; i < 2; ++i)
                ldsm4(af[i], abuf + (aRowOfs + (uint32_t)(i * 16 * LDH + ks * 16)) * 2);
            #pragma unroll
            for (int j = 0; j < 4; ++j)
                ldsm2(bfr[j], bbuf + (bRowOfs + (uint32_t)(j * 8 * LDH + ks * 16)) * 2);
            #pragma unroll
            for (int i = 0; i < 2; ++i)
                #pragma unroll
                for (int j = 0; j < 4; ++j)
                    mma_f16(acc[i][j], af[i], bfr[j]);
        }
    };

    const int nk = K / 32;
    issue(0, 0);
    issue(1, 32);
    issue(2, 64);
    for (int i = 0; i < nk; ++i) {
        if (i + 2 < nk)      { CP_WAIT(2); }
        else if (i + 1 < nk) { CP_WAIT(1); }
        else                 { CP_WAIT(0); }
        __syncthreads();
        const int nx = i + 3;
        if (nx < nk) issue(nx & 3, nx * 32);
        compute(i & 3);
    }

    #pragma unroll
    for (int i = 0; i < 2; ++i) {
        const int row = blockIdx.y * 128 + wm + i * 16 + l4;
        #pragma unroll
        for (int j = 0; j < 4; ++j) {
            const int col = blockIdx.x * 128 + wn + j * 8 + lm * 2;
            if (KSPLIT) {
                float* Cf = (float*)C;
                *reinterpret_cast<float2*>(Cf + (size_t)row * N + col) =
                    make_float2(acc[i][j][0], acc[i][j][1]);
                *reinterpret_cast<float2*>(Cf + (size_t)(row + 8) * N + col) =
                    make_float2(acc[i][j][2], acc[i][j][3]);
            } else {
                const float bv0 = bia[col], bv1 = bia[col + 1];
                float v0 = acc[i][j][0] + bv0;
                float v1 = acc[i][j][1] + bv1;
                float v2 = acc[i][j][2] + bv0;
                float v3 = acc[i][j][3] + bv1;
                if (GELU) {
                    v0 = 0.5f * v0 * (1.f + erff(v0 * 0.70710678118654752f));
                    v1 = 0.5f * v1 * (1.f + erff(v1 * 0.70710678118654752f));
                    v2 = 0.5f * v2 * (1.f + erff(v2 * 0.70710678118654752f));
                    v3 = 0.5f * v3 * (1.f + erff(v3 * 0.70710678118654752f));
                }
                if (OUT16) {
                    __half* Ch = (__half*)C;
                    *reinterpret_cast<uint32_t*>(Ch + (size_t)row * N + col)       = pkh2(v0, v1);
                    *reinterpret_cast<uint32_t*>(Ch + (size_t)(row + 8) * N + col) = pkh2(v2, v3);
                } else {
                    float* Cf = (float*)C;
                    *reinterpret_cast<float2*>(Cf + (size_t)row * N + col)       = make_float2(v0, v1);
                    *reinterpret_cast<float2*>(Cf + (size_t)(row + 8) * N + col) = make_float2(v2, v3);
                }
            }
        }
    }
}

// ---------------- Attention: FA2-style fp16 MMA, double-buffered K/V --------
#define AT_LDH 72   // halves per smem row (144B): ldmatrix phases conflict-free
__global__ __launch_bounds__(128)
void attn_f16(const __half* __restrict__ q,
              const __half* __restrict__ k,
              const __half* __restrict__ v,
              const float* __restrict__ mask,
              __half* __restrict__ out)
{
    __shared__ __half Ks[2][64][AT_LDH];
    __shared__ __half Vs[2][64][AT_LDH];
    __shared__ float  msk[2][64];

    const int b    = blockIdx.z;
    const int h    = blockIdx.y;
    const int q0   = blockIdx.x * 64;
    const int tid  = threadIdx.x;
    const int w    = tid >> 5;
    const int lane = tid & 31;
    const int g    = lane >> 2;
    const int tg   = lane & 3;
    const int lB   = lane & 15;
    const int rBk  = lB & 7;
    const int kBk  = (lB >> 3) * 8;

    const size_t boff = (size_t)b * SS;
    const int hofs = h * HD;
    const int rlo  = q0 + w * 16 + g;

    const uint32_t ks0 = (uint32_t)__cvta_generic_to_shared(&Ks[0][0][0]);
    const uint32_t vs0 = (uint32_t)__cvta_generic_to_shared(&Vs[0][0][0]);
    constexpr uint32_t BUFB = 64 * AT_LDH * 2;

    auto issue = [&](int t) {
        const int kt = t * 64;
        const uint32_t bo = (uint32_t)(t & 1) * BUFB;
        #pragma unroll
        for (int it = 0; it < 4; ++it) {
            const int c  = it * 128 + tid;
            const int r  = c >> 3, cc = (c & 7) * 8;
            const size_t gofs = (boff + kt + r) * DD + hofs + cc;
            cpa16(ks0 + bo + (uint32_t)(r * AT_LDH + cc) * 2, k + gofs);
            cpa16(vs0 + bo + (uint32_t)(r * AT_LDH + cc) * 2, v + gofs);
        }
        CP_COMMIT();
        if (tid < 64) msk[t & 1][tid] = -10000.f * (1.f - mask[boff + kt + tid]);
    };

    uint32_t qa[4][4];
    {
        const __half* qlo = q + (boff + rlo) * DD + hofs;
        const __half* qhi = qlo + 8 * DD;
        const __half2 s = __float2half2_rn(0.125f);
        #pragma unroll
        for (int ks = 0; ks < 4; ++ks) {
            const int c0 = ks * 16 + 2 * tg;
            __half2 t0 = __hmul2(*reinterpret_cast<const __half2*>(qlo + c0), s);
            __half2 t1 = __hmul2(*reinterpret_cast<const __half2*>(qhi + c0), s);
            __half2 t2 = __hmul2(*reinterpret_cast<const __half2*>(qlo + c0 + 8), s);
            __half2 t3 = __hmul2(*reinterpret_cast<const __half2*>(qhi + c0 + 8), s);
            qa[ks][0] = *reinterpret_cast<uint32_t*>(&t0);
            qa[ks][1] = *reinterpret_cast<uint32_t*>(&t1);
            qa[ks][2] = *reinterpret_cast<uint32_t*>(&t2);
            qa[ks][3] = *reinterpret_cast<uint32_t*>(&t3);
        }
    }

    float o[8][4];
    #pragma unroll
    for (int j = 0; j < 8; ++j)
        #pragma unroll
        for (int r = 0; r < 4; ++r) o[j][r] = 0.f;
    float mx_lo = -1e30f, mx_hi = -1e30f, l_lo = 0.f, l_hi = 0.f;

    constexpr int NT = SS / 64;
    issue(0);

    for (int t = 0; t < NT; ++t) {
        if (t + 1 < NT) {
            issue(t + 1);
            CP_WAIT(1);
        } else {
            CP_WAIT(0);
        }
        __syncthreads();

        const int buf = t & 1;
        const uint32_t ks_base = ks0 + (uint32_t)buf * BUFB;
        const uint32_t vs_base = vs0 + (uint32_t)buf * BUFB;

        float sc[8][4];
        #pragma unroll
        for (int j = 0; j < 8; ++j) {
            sc[j][0] = sc[j][1] = sc[j][2] = sc[j][3] = 0.f;
            #pragma unroll
            for (int ks = 0; ks < 4; ++ks) {
                uint32_t bb[2];
                ldsm2(bb, ks_base + (uint32_t)((j * 8 + rBk) * AT_LDH + kBk + ks * 16) * 2);
                mma_f16(sc[j], qa[ks], bb);
            }
        }

        float nm_lo = mx_lo, nm_hi = mx_hi;
        #pragma unroll
        for (int j = 0; j < 8; ++j) {
            const float m0 = msk[buf][j * 8 + 2 * tg], m1 = msk[buf][j * 8 + 2 * tg + 1];
            sc[j][0] += m0; sc[j][1] += m1; sc[j][2] += m0; sc[j][3] += m1;
            nm_lo = fmaxf(nm_lo, fmaxf(sc[j][0], sc[j][1]));
            nm_hi = fmaxf(nm_hi, fmaxf(sc[j][2], sc[j][3]));
        }
        nm_lo = fmaxf(nm_lo, __shfl_xor_sync(0xFFFFFFFFu, nm_lo, 1));
        nm_lo = fmaxf(nm_lo, __shfl_xor_sync(0xFFFFFFFFu, nm_lo, 2));
        nm_hi = fmaxf(nm_hi, __shfl_xor_sync(0xFFFFFFFFu, nm_hi, 1));
        nm_hi = fmaxf(nm_hi, __shfl_xor_sync(0xFFFFFFFFu, nm_hi, 2));
        const float cor_lo = __expf(mx_lo - nm_lo);
        const float cor_hi = __expf(mx_hi - nm_hi);
        mx_lo = nm_lo; mx_hi = nm_hi;

        uint32_t pa[4][4];
        float sl_lo = 0.f, sl_hi = 0.f;
        #pragma unroll
        for (int j = 0; j < 8; ++j) {
            const float p0 = __expf(sc[j][0] - mx_lo);
            const float p1 = __expf(sc[j][1] - mx_lo);
            const float p2 = __expf(sc[j][2] - mx_hi);
            const float p3 = __expf(sc[j][3] - mx_hi);
            sl_lo += p0 + p1; sl_hi += p2 + p3;
            const int ks = j >> 1;
            if ((j & 1) == 0) {
                pa[ks][0] = pkh2(p0, p1);
                pa[ks][1] = pkh2(p2, p3);
            } else {
                pa[ks][2] = pkh2(p0, p1);
                pa[ks][3] = pkh2(p2, p3);
            }
        }
        sl_lo += __shfl_xor_sync(0xFFFFFFFFu, sl_lo, 1);
        sl_lo += __shfl_xor_sync(0xFFFFFFFFu, sl_lo, 2);
        sl_hi += __shfl_xor_sync(0xFFFFFFFFu, sl_hi, 1);
        sl_hi += __shfl_xor_sync(0xFFFFFFFFu, sl_hi, 2);
        l_lo = l_lo * cor_lo + sl_lo;
        l_hi = l_hi * cor_hi + sl_hi;
        #pragma unroll
        for (int j = 0; j < 8; ++j) {
            o[j][0] *= cor_lo; o[j][1] *= cor_lo;
            o[j][2] *= cor_hi; o[j][3] *= cor_hi;
        }

        #pragma unroll
        for (int ks = 0; ks < 4; ++ks) {
            #pragma unroll
            for (int j = 0; j < 8; ++j) {
                uint32_t bv[2];
                ldsm2t(bv, vs_base + (uint32_t)((ks * 16 + lB) * AT_LDH + j * 8) * 2);
                mma_f16(o[j], pa[ks], bv);
            }
        }
        __syncthreads();
    }

    const float inv_lo = 1.f / l_lo;
    const float inv_hi = 1.f / l_hi;
    __half* olo = out + (boff + rlo) * DD + hofs;
    __half* ohi = olo + 8 * DD;
    #pragma unroll
    for (int j = 0; j < 8; ++j) {
        *reinterpret_cast<uint32_t*>(olo + j * 8 + 2 * tg) =
            pkh2(o[j][0] * inv_lo, o[j][1] * inv_lo);
        *reinterpret_cast<uint32_t*>(ohi + j * 8 + 2 * tg) =
            pkh2(o[j][2] * inv_hi, o[j][3] * inv_hi);
    }
}

// ---------------- Fused 2-partial residual + bias + LayerNorm ---------------
// v = a + p0 + p1 + bias;  out = gamma * normalize(v) + beta  (float4, 192 thr)
template<int OUT16>
__global__ __launch_bounds__(192)
void ln3_kernel(const float* __restrict__ a,
                const float* __restrict__ p0, const float* __restrict__ p1,
                const float* __restrict__ bias,
                const float* __restrict__ gamma, const float* __restrict__ beta,
                float* __restrict__ out, __half* __restrict__ out16)
{
    const size_t base = (size_t)blockIdx.x * DD;
    const int t = threadIdx.x, c = t * 4;

    float4 v  = *reinterpret_cast<const float4*>(a + base + c);
    const float4 q0 = *reinterpret_cast<const float4*>(p0 + base + c);
    const float4 q1 = *reinterpret_cast<const float4*>(p1 + base + c);
    const float4 bb = *reinterpret_cast<const float4*>(bias + c);
    v.x += q0.x + q1.x + bb.x;
    v.y += q0.y + q1.y + bb.y;
    v.z += q0.z + q1.z + bb.z;
    v.w += q0.w + q1.w + bb.w;

    float s  = v.x + v.y + v.z + v.w;
    float ss = v.x * v.x + v.y * v.y + v.z * v.z + v.w * v.w;
    #pragma unroll
    for (int o = 16; o > 0; o >>= 1) {
        s  += __shfl_xor_sync(0xFFFFFFFFu, s,  o);
        ss += __shfl_xor_sync(0xFFFFFFFFu, ss, o);
    }
    __shared__ float rs[6], rss[6], stats[2];
    const int wid = t >> 5, lid = t & 31;
    if (lid == 0) { rs[wid] = s; rss[wid] = ss; }
    __syncthreads();
    if (t == 0) {
        float S = 0.f, SSq = 0.f;
        #pragma unroll
        for (int i = 0; i < 6; ++i) { S += rs[i]; SSq += rss[i]; }
        const float mu  = S * (1.f / DD);
        const float var = SSq * (1.f / DD) - mu * mu;
        stats[0] = mu;
        stats[1] = rsqrtf(var + 1e-12f);
    }
    __syncthreads();
    const float mu = stats[0], rstd = stats[1];

    const float4 g  = *reinterpret_cast<const float4*>(gamma + c);
    const float4 be = *reinterpret_cast<const float4*>(beta + c);
    float4 o4;
    o4.x = g.x * (v.x - mu) * rstd + be.x;
    o4.y = g.y * (v.y - mu) * rstd + be.y;
    o4.z = g.z * (v.z - mu) * rstd + be.z;
    o4.w = g.w * (v.w - mu) * rstd + be.w;
    *reinterpret_cast<float4*>(out + base + c) = o4;
    if (OUT16) {
        *reinterpret_cast<uint2*>(out16 + base + c) =
            make_uint2(pkh2(o4.x, o4.y), pkh2(o4.z, o4.w));
    }
}

// ---------------- launcher -------------------------------------------------
extern "C" void kernel_launch(void* const* d_in, const int* in_sizes, int n_in,
                              void* d_out, int out_size)
{
    const float* x    = (const float*)d_in[0];
    const float* mask = (const float*)d_in[1];
    const float* Wq   = (const float*)d_in[2];
    const float* bq   = (const float*)d_in[3];
    const float* Wk   = (const float*)d_in[4];
    const float* bk   = (const float*)d_in[5];
    const float* Wv   = (const float*)d_in[6];
    const float* bv   = (const float*)d_in[7];
    const float* Wp   = (const float*)d_in[8];
    const float* bp   = (const float*)d_in[9];
    const float* g1   = (const float*)d_in[10];
    const float* be1  = (const float*)d_in[11];
    const float* W1   = (const float*)d_in[12];
    const float* bf1  = (const float*)d_in[13];
    const float* W2   = (const float*)d_in[14];
    const float* bf2  = (const float*)d_in[15];
    const float* g2   = (const float*)d_in[16];
    const float* be2  = (const float*)d_in[17];
    float* outp = (float*)d_out;

    __half *phx, *phwq, *phwk, *phwv, *phwp, *phw1, *phw2;
    __half *phq, *phk, *phv, *phat, *phx1, *phff;
    float *ppa, *ppb, *px1f, *pfa, *pfb;
    cudaGetSymbolAddress((void**)&phx,  h_x);
    cudaGetSymbolAddress((void**)&phwq, h_wq);
    cudaGetSymbolAddress((void**)&phwk, h_wk);
    cudaGetSymbolAddress((void**)&phwv, h_wv);
    cudaGetSymbolAddress((void**)&phwp, h_wp);
    cudaGetSymbolAddress((void**)&phw1, h_w1);
    cudaGetSymbolAddress((void**)&phw2, h_w2);
    cudaGetSymbolAddress((void**)&phq,  h_q);
    cudaGetSymbolAddress((void**)&phk,  h_k);
    cudaGetSymbolAddress((void**)&phv,  h_v);
    cudaGetSymbolAddress((void**)&phat, h_at);
    cudaGetSymbolAddress((void**)&phx1, h_x1);
    cudaGetSymbolAddress((void**)&phff, h_ff);
    cudaGetSymbolAddress((void**)&ppa,  g_pa);
    cudaGetSymbolAddress((void**)&ppb,  g_pb);
    cudaGetSymbolAddress((void**)&px1f, g_x1f);
    cudaGetSymbolAddress((void**)&pfa,  g_fa);
    cudaGetSymbolAddress((void**)&pfb,  g_fb);

    cudaFuncSetAttribute(gemm_a16<0, 1, 0>, cudaFuncAttributeMaxDynamicSharedMemorySize, GT_SMEM);
    cudaFuncSetAttribute(gemm_a16<1, 1, 0>, cudaFuncAttributeMaxDynamicSharedMemorySize, GT_SMEM);
    cudaFuncSetAttribute(gemm_a16<0, 0, 1>, cudaFuncAttributeMaxDynamicSharedMemorySize, GT_SMEM);

    // single fused fp32->fp16 conversion launch (inputs + weights)
    {
        CvtArgs ca;
        const float* srcs[7] = { x, Wq, Wk, Wv, Wp, W1, W2 };
        __half*      dsts[7] = { phx, phwq, phwk, phwv, phwp, phw1, phw2 };
        const int    ns[7]   = { MM * DD, DD * DD, DD * DD, DD * DD, DD * DD,
                                 DFF * DD, DD * DFF };
        int cum = 0;
        for (int i = 0; i < 7; ++i) {
            ca.src[i] = srcs[i];
            ca.dst[i] = dsts[i];
            ca.cum[i] = cum;
            cum += ns[i] / 8;
        }
        ca.cum[7] = cum;
        f2h_multi<<<(cum + 255) / 256, 256>>>(ca);
    }

    // QKV projections (z selects W/bias/out): 576 blocks x 512 thr
    gemm_a16<0, 1, 0><<<dim3(DD / 128, MM / 128, 3), 512, GT_SMEM>>>(
        DD, DD, DD, phx, phwq, bq, phq, phwk, bk, phk, phwv, bv, phv);

    // Attention (fp16 in/out, double-buffered K/V)
    attn_f16<<<dim3(SS / 64, HH, BB), 128>>>(phq, phk, phv, mask, phat);

    // Output projection, K split in 2 (z): partials -> LN1 fuses +x +bias
    gemm_a16<0, 0, 1><<<dim3(DD / 128, MM / 128, 2), 512, GT_SMEM>>>(
        DD / 2, DD, DD, phat, phwp, bp, ppa, nullptr, nullptr, ppb,
        nullptr, nullptr, nullptr);
    ln3_kernel<1><<<MM, 192>>>(x, ppa, ppb, bp, g1, be1, px1f, phx1);

    // FFN1 (+GELU): 768 blocks
    gemm_a16<1, 1, 0><<<dim3(DFF / 128, MM / 128, 1), 512, GT_SMEM>>>(
        DD, DD, DFF, phx1, phw1, bf1, phff, phw1, bf1, phff, phw1, bf1, phff);

    // FFN2, K split in 2 (z): partials -> LN2 fuses +x1 +bias
    gemm_a16<0, 0, 1><<<dim3(DD / 128, MM / 128, 2), 512, GT_SMEM>>>(
        DFF / 2, DFF, DD, phff, phw2, bf2, pfa, nullptr, nullptr, pfb,
        nullptr, nullptr, nullptr);
    ln3_kernel<0><<<MM, 192>>>(px1f, pfa, pfb, bf2, g2, be2, outp, nullptr);
}